// round 1
// baseline (speedup 1.0000x reference)
#include <cuda_runtime.h>
#include <cstdint>
#include <cstddef>

#define B_  4
#define T_  2048
#define C_  2048
#define H_  16
#define HD_ 128

// ---------------- scratch (static __device__ — no allocations allowed) ----------
__device__ float g_qkv[(size_t)B_ * T_ * 3 * C_];          // [B*T, 3C]
__device__ float g_q[(size_t)B_ * H_ * T_ * HD_];          // [B,H,T,HD]
__device__ float g_k[(size_t)B_ * H_ * T_ * HD_];
__device__ float g_v[(size_t)B_ * H_ * T_ * HD_];
__device__ float g_y[(size_t)B_ * T_ * C_];                // attention out [B,T,C]

// ---------------- SGEMM: C = A[MxK] * B[KxN], all row-major, dims divisible ----
// 128x128 block, BK=16, 256 threads, 8x8 microtile (cols split tx*4 and 64+tx*4)
__global__ __launch_bounds__(256) void sgemm_kernel(
    const float* __restrict__ A, const float* __restrict__ Bm,
    float* __restrict__ Cm, int M, int N, int K)
{
    constexpr int BM = 128, BN = 128, BK = 16;
    __shared__ float As[BK][BM];   // transposed A tile
    __shared__ float Bs[BK][BN];

    const int bx = blockIdx.x;     // N tile
    const int by = blockIdx.y;     // M tile
    const int tid = threadIdx.x;
    const int tx = tid & 15;       // 16 col-groups
    const int ty = tid >> 4;       // 16 row-groups

    const float* Ablk = A + (size_t)by * BM * K;
    const float* Bblk = Bm + (size_t)bx * BN;

    float acc[8][8];
    #pragma unroll
    for (int i = 0; i < 8; i++)
        #pragma unroll
        for (int j = 0; j < 8; j++) acc[i][j] = 0.f;

    for (int k0 = 0; k0 < K; k0 += BK) {
        // load A tile: 128 rows x 16 cols = 512 float4
        #pragma unroll
        for (int it = 0; it < 2; it++) {
            int idx = tid + it * 256;            // 0..511
            int r  = idx >> 2;                   // 0..127
            int c4 = (idx & 3) << 2;             // 0,4,8,12
            float4 v = *(const float4*)(Ablk + (size_t)r * K + k0 + c4);
            As[c4 + 0][r] = v.x; As[c4 + 1][r] = v.y;
            As[c4 + 2][r] = v.z; As[c4 + 3][r] = v.w;
        }
        // load B tile: 16 rows x 128 cols = 512 float4
        #pragma unroll
        for (int it = 0; it < 2; it++) {
            int idx = tid + it * 256;
            int r  = idx >> 5;                   // 0..15
            int c4 = (idx & 31) << 2;            // 0..124
            *(float4*)&Bs[r][c4] = *(const float4*)(Bblk + (size_t)(k0 + r) * N + c4);
        }
        __syncthreads();

        #pragma unroll
        for (int kk = 0; kk < BK; kk++) {
            float4 a0 = *(const float4*)&As[kk][ty * 8];
            float4 a1 = *(const float4*)&As[kk][ty * 8 + 4];
            float4 b0 = *(const float4*)&Bs[kk][tx * 4];
            float4 b1 = *(const float4*)&Bs[kk][64 + tx * 4];
            float a[8] = {a0.x,a0.y,a0.z,a0.w,a1.x,a1.y,a1.z,a1.w};
            float b[8] = {b0.x,b0.y,b0.z,b0.w,b1.x,b1.y,b1.z,b1.w};
            #pragma unroll
            for (int i = 0; i < 8; i++)
                #pragma unroll
                for (int j = 0; j < 8; j++)
                    acc[i][j] += a[i] * b[j];
        }
        __syncthreads();
    }

    float* Cblk = Cm + (size_t)by * BM * N + (size_t)bx * BN;
    #pragma unroll
    for (int i = 0; i < 8; i++) {
        size_t row = (size_t)(ty * 8 + i) * N;
        float4 v0 = make_float4(acc[i][0], acc[i][1], acc[i][2], acc[i][3]);
        float4 v1 = make_float4(acc[i][4], acc[i][5], acc[i][6], acc[i][7]);
        *(float4*)(Cblk + row + tx * 4)      = v0;
        *(float4*)(Cblk + row + 64 + tx * 4) = v1;
    }
}

// ---------------- RoPE + transpose: qkv[B,T,3C] -> q/k/v [B,H,T,HD] ------------
__global__ __launch_bounds__(256) void rope_kernel(
    const float* __restrict__ qkv, const float* __restrict__ rope,
    float* __restrict__ q, float* __restrict__ k, float* __restrict__ v)
{
    int idx = blockIdx.x * 256 + threadIdx.x;   // B*T*H*(HD/2) = 8388608
    int p = idx & 63;
    int h = (idx >> 6) & 15;
    int t = (idx >> 10) & 2047;
    int b = idx >> 21;

    float2 cs = ((const float2*)rope)[t * 64 + p];
    size_t base_in = ((size_t)(b * T_ + t)) * (3 * C_) + h * HD_ + p * 2;
    float2 qv = *(const float2*)(qkv + base_in);
    float2 kv = *(const float2*)(qkv + base_in + C_);
    float2 vv = *(const float2*)(qkv + base_in + 2 * C_);

    float2 qo = make_float2(qv.x * cs.x - qv.y * cs.y, qv.y * cs.x + qv.x * cs.y);
    float2 ko = make_float2(kv.x * cs.x - kv.y * cs.y, kv.y * cs.x + kv.x * cs.y);

    size_t base_out = ((size_t)((b * H_ + h) * T_ + t)) * HD_ + p * 2;
    *(float2*)(q + base_out) = qo;
    *(float2*)(k + base_out) = ko;
    *(float2*)(v + base_out) = vv;
}

// ---------------- Flash attention (fp32, causal), 64x64 tiles ------------------
// grid: (T/64, B*H); 256 threads as 16(tx) x 16(ty).
// thread owns S rows ty*4..+3, S cols tx*4..+3; O cols {tx*4..+3, 64+tx*4..+3}.
__global__ __launch_bounds__(256) void attn_kernel(
    const float* __restrict__ Qg_, const float* __restrict__ Kg_,
    const float* __restrict__ Vg_, float* __restrict__ Y)
{
    extern __shared__ float sm[];
    float* Qs = sm;               // 64*128
    float* Ks = Qs + 64 * 128;    // 64*128, XOR-swizzled float4 chunks
    float* Vs = Ks + 64 * 128;    // 64*128
    float* Ss = Vs + 64 * 128;    // 64*64 (P tile)

    const int qt = blockIdx.x;
    const int bh = blockIdx.y;
    const int b  = bh >> 4, h = bh & 15;
    const int tid = threadIdx.x;
    const int tx = tid & 15, ty = tid >> 4;
    const float scale = 0.08838834764831845f;   // 1/sqrt(128)

    const size_t head_off = (size_t)bh * T_ * HD_;
    const float4* Qg = (const float4*)(Qg_ + head_off + (size_t)qt * 64 * HD_);

    // load Q tile (pre-scaled)
    for (int i = tid; i < 64 * HD_ / 4; i += 256) {
        float4 v = Qg[i];
        v.x *= scale; v.y *= scale; v.z *= scale; v.w *= scale;
        ((float4*)Qs)[i] = v;
    }

    float m[4], l[4], o[4][8];
    #pragma unroll
    for (int i = 0; i < 4; i++) {
        m[i] = -1e30f; l[i] = 0.f;
        #pragma unroll
        for (int c = 0; c < 8; c++) o[i][c] = 0.f;
    }

    const int sw = tx & 7;

    for (int kt = 0; kt <= qt; kt++) {
        __syncthreads();   // protect Ks/Vs/Ss reuse (and Q load on first iter)
        const float4* Kg = (const float4*)(Kg_ + head_off + (size_t)kt * 64 * HD_);
        const float4* Vg = (const float4*)(Vg_ + head_off + (size_t)kt * 64 * HD_);
        for (int i = tid; i < 2048; i += 256) {
            int c = i >> 5, d4 = i & 31;
            ((float4*)Ks)[c * 32 + (d4 ^ ((c >> 2) & 7))] = Kg[i];  // swizzled
            ((float4*)Vs)[i] = Vg[i];
        }
        __syncthreads();

        // S = Q K^T  (4x4 microtile, conflict-free LDS.128 both operands)
        float s[4][4];
        #pragma unroll
        for (int i = 0; i < 4; i++)
            #pragma unroll
            for (int j = 0; j < 4; j++) s[i][j] = 0.f;

        #pragma unroll 4
        for (int d4 = 0; d4 < 32; d4++) {
            float4 q4[4], k4[4];
            #pragma unroll
            for (int i = 0; i < 4; i++)
                q4[i] = ((const float4*)Qs)[(ty * 4 + i) * 32 + d4];
            #pragma unroll
            for (int j = 0; j < 4; j++)
                k4[j] = ((const float4*)Ks)[(tx * 4 + j) * 32 + (d4 ^ sw)];
            #pragma unroll
            for (int i = 0; i < 4; i++)
                #pragma unroll
                for (int j = 0; j < 4; j++) {
                    s[i][j] += q4[i].x * k4[j].x;
                    s[i][j] += q4[i].y * k4[j].y;
                    s[i][j] += q4[i].z * k4[j].z;
                    s[i][j] += q4[i].w * k4[j].w;
                }
        }

        // causal mask (only diagonal tile)
        if (kt == qt) {
            #pragma unroll
            for (int i = 0; i < 4; i++)
                #pragma unroll
                for (int j = 0; j < 4; j++)
                    if (tx * 4 + j > ty * 4 + i) s[i][j] = -1e30f;
        }

        // online softmax per row (stats replicated across the 16 tx lanes)
        #pragma unroll
        for (int i = 0; i < 4; i++) {
            float rm = fmaxf(fmaxf(s[i][0], s[i][1]), fmaxf(s[i][2], s[i][3]));
            #pragma unroll
            for (int off = 8; off; off >>= 1)
                rm = fmaxf(rm, __shfl_xor_sync(0xffffffffu, rm, off));
            float mn = fmaxf(m[i], rm);
            float corr = __expf(m[i] - mn);
            m[i] = mn;
            float rs = 0.f;
            #pragma unroll
            for (int j = 0; j < 4; j++) { s[i][j] = __expf(s[i][j] - mn); rs += s[i][j]; }
            #pragma unroll
            for (int off = 8; off; off >>= 1)
                rs += __shfl_xor_sync(0xffffffffu, rs, off);
            l[i] = l[i] * corr + rs;
            #pragma unroll
            for (int c = 0; c < 8; c++) o[i][c] *= corr;
            *(float4*)&Ss[(ty * 4 + i) * 64 + tx * 4] =
                make_float4(s[i][0], s[i][1], s[i][2], s[i][3]);
        }
        __syncthreads();

        // O += P V
        #pragma unroll 4
        for (int kk = 0; kk < 64; kk++) {
            float p0 = Ss[(ty * 4 + 0) * 64 + kk];
            float p1 = Ss[(ty * 4 + 1) * 64 + kk];
            float p2 = Ss[(ty * 4 + 2) * 64 + kk];
            float p3 = Ss[(ty * 4 + 3) * 64 + kk];
            float4 v0 = ((const float4*)Vs)[kk * 32 + tx];
            float4 v1 = ((const float4*)Vs)[kk * 32 + 16 + tx];
            float p[4] = {p0, p1, p2, p3};
            #pragma unroll
            for (int i = 0; i < 4; i++) {
                o[i][0] += p[i] * v0.x; o[i][1] += p[i] * v0.y;
                o[i][2] += p[i] * v0.z; o[i][3] += p[i] * v0.w;
                o[i][4] += p[i] * v1.x; o[i][5] += p[i] * v1.y;
                o[i][6] += p[i] * v1.z; o[i][7] += p[i] * v1.w;
            }
        }
    }

    // write out: y[b, qt*64+row, h*HD + col]
    float* Yb = Y + ((size_t)(b * T_ + qt * 64)) * C_ + h * HD_;
    #pragma unroll
    for (int i = 0; i < 4; i++) {
        float inv = 1.f / l[i];
        size_t row = (size_t)(ty * 4 + i) * C_;
        float4 v0 = make_float4(o[i][0]*inv, o[i][1]*inv, o[i][2]*inv, o[i][3]*inv);
        float4 v1 = make_float4(o[i][4]*inv, o[i][5]*inv, o[i][6]*inv, o[i][7]*inv);
        *(float4*)(Yb + row + tx * 4)      = v0;
        *(float4*)(Yb + row + 64 + tx * 4) = v1;
    }
}

// ---------------- launch --------------------------------------------------------
extern "C" void kernel_launch(void* const* d_in, const int* in_sizes, int n_in,
                              void* d_out, int out_size)
{
    const float* x     = (const float*)d_in[0];
    const float* rope  = (const float*)d_in[1];
    const float* Wqkv  = (const float*)d_in[2];
    const float* Wproj = (const float*)d_in[3];
    float* out = (float*)d_out;

    float *qkv, *q, *k, *v, *y;
    cudaGetSymbolAddress((void**)&qkv, g_qkv);
    cudaGetSymbolAddress((void**)&q,   g_q);
    cudaGetSymbolAddress((void**)&k,   g_k);
    cudaGetSymbolAddress((void**)&v,   g_v);
    cudaGetSymbolAddress((void**)&y,   g_y);

    // 1) qkv = x @ Wqkv   [8192 x 6144 x 2048]
    dim3 g1((3 * C_) / 128, (B_ * T_) / 128);
    sgemm_kernel<<<g1, 256>>>(x, Wqkv, qkv, B_ * T_, 3 * C_, C_);

    // 2) RoPE + transpose to [B,H,T,HD]
    rope_kernel<<<(B_ * T_ * H_ * (HD_ / 2)) / 256, 256>>>(qkv, rope, q, k, v);

    // 3) causal flash attention -> y [B,T,C]
    const int smem_bytes = (3 * 64 * 128 + 64 * 64) * 4;   // 114688
    cudaFuncSetAttribute(attn_kernel, cudaFuncAttributeMaxDynamicSharedMemorySize,
                         smem_bytes);
    attn_kernel<<<dim3(T_ / 64, B_ * H_), 256, smem_bytes>>>(q, k, v, y);

    // 4) out = y @ Wproj  [8192 x 2048 x 2048]
    dim3 g2(C_ / 128, (B_ * T_) / 128);
    sgemm_kernel<<<g2, 256>>>(y, Wproj, out, B_ * T_, C_, C_);
}

// round 4
// speedup vs baseline: 1.9582x; 1.9582x over previous
#include <cuda_runtime.h>
#include <cstdint>
#include <cstddef>

#define B_  4
#define T_  2048
#define C_  2048
#define H_  16
#define HD_ 128

// ---------------- scratch (static __device__ — no allocations allowed) ----------
__device__ float g_qkv[(size_t)B_ * T_ * 3 * C_];          // [B*T, 3C]
__device__ float g_q[(size_t)B_ * H_ * T_ * HD_];          // [B,H,T,HD]
__device__ float g_k[(size_t)B_ * H_ * T_ * HD_];
__device__ float g_v[(size_t)B_ * H_ * T_ * HD_];
__device__ float g_y[(size_t)B_ * T_ * C_];                // attention out [B,T,C]
__device__ float g_wqkvT[(size_t)3 * C_ * C_];             // Wqkv^T  [3C, C]
__device__ float g_wprojT[(size_t)C_ * C_];                // Wproj^T [C, C]

// ---------------- small helpers -------------------------------------------------
__device__ __forceinline__ uint32_t f2tf(float x) {
    uint32_t u;
    asm("cvt.rna.tf32.f32 %0, %1;" : "=r"(u) : "f"(x));
    return u;
}
__device__ __forceinline__ void mma_tf32(float* d, const uint32_t* a,
                                         const uint32_t* b) {
    asm volatile(
        "mma.sync.aligned.m16n8k8.row.col.f32.tf32.tf32.f32 "
        "{%0,%1,%2,%3}, {%4,%5,%6,%7}, {%8,%9}, {%0,%1,%2,%3};"
        : "+f"(d[0]), "+f"(d[1]), "+f"(d[2]), "+f"(d[3])
        : "r"(a[0]), "r"(a[1]), "r"(a[2]), "r"(a[3]), "r"(b[0]), "r"(b[1]));
}

// ===================== TF32 mma.sync GEMM =======================================
// C[M,N] = A[M,K] * Bt[N,K]^T ; A row-major [M,K], Bt row-major [N,K] (K-major).
// CTA tile 128x256, BK=16, 256 threads = 8 warps (2 M x 4 N), warp tile 64x64.
// Smem rows padded to 20 floats -> conflict-free scalar fragment loads.
#define APITCH 20
#define ABUF_FLOATS (128 * APITCH)            // 2560
#define BBUF_FLOATS (256 * APITCH)            // 5120
#define BUF_FLOATS  (ABUF_FLOATS + BBUF_FLOATS)  // 7680
#define GSM_BYTES   (2 * BUF_FLOATS * 4)      // 61440

__global__ __launch_bounds__(256, 1) void gemm_tf32(
    const float* __restrict__ A, const float* __restrict__ Bt,
    float* __restrict__ Cm, int M, int N, int K)
{
    extern __shared__ float sm[];
    const int tid  = threadIdx.x;
    const int wid  = tid >> 5;
    const int lane = tid & 31;
    const int g    = lane >> 2;      // groupID 0..7
    const int c    = lane & 3;       // threadID_in_group 0..3
    const int warp_m = wid & 1;      // 0..1  (64 rows each)
    const int warp_n = wid >> 1;     // 0..3  (64 cols each)

    const size_t m0 = (size_t)blockIdx.x * 128;
    const size_t n0 = (size_t)blockIdx.y * 256;

    // per-thread global load coordinates (A: 512 float4, B: 1024 float4)
    const int ar[2]  = { (tid + 0)   >> 2, (tid + 256) >> 2 };
    const int akk[2] = { ((tid + 0)   & 3) << 2, ((tid + 256) & 3) << 2 };
    int br[4], bkk[4];
    #pragma unroll
    for (int j = 0; j < 4; j++) {
        br[j]  = (tid + j * 256) >> 2;
        bkk[j] = ((tid + j * 256) & 3) << 2;
    }

    float acc[4][8][4];
    #pragma unroll
    for (int mi = 0; mi < 4; mi++)
        #pragma unroll
        for (int ni = 0; ni < 8; ni++)
            #pragma unroll
            for (int q = 0; q < 4; q++) acc[mi][ni][q] = 0.f;

    float4 pa[2], pb[4];

    // ---- preload tile 0
    #pragma unroll
    for (int j = 0; j < 2; j++)
        pa[j] = *(const float4*)(A + (m0 + ar[j]) * K + akk[j]);
    #pragma unroll
    for (int j = 0; j < 4; j++)
        pb[j] = *(const float4*)(Bt + (n0 + br[j]) * K + bkk[j]);
    {
        float* As = sm; float* Bs = sm + ABUF_FLOATS;
        #pragma unroll
        for (int j = 0; j < 2; j++) {
            uint32_t* p = (uint32_t*)(As + ar[j] * APITCH + akk[j]);
            p[0] = f2tf(pa[j].x); p[1] = f2tf(pa[j].y);
            p[2] = f2tf(pa[j].z); p[3] = f2tf(pa[j].w);
        }
        #pragma unroll
        for (int j = 0; j < 4; j++) {
            uint32_t* p = (uint32_t*)(Bs + br[j] * APITCH + bkk[j]);
            p[0] = f2tf(pb[j].x); p[1] = f2tf(pb[j].y);
            p[2] = f2tf(pb[j].z); p[3] = f2tf(pb[j].w);
        }
    }
    __syncthreads();

    const int niter = K >> 4;    // BK = 16
    for (int it = 0; it < niter; ++it) {
        const int bs = it & 1;
        const bool more = (it + 1 < niter);

        // prefetch next tile into registers
        if (more) {
            const int k0 = (it + 1) << 4;
            #pragma unroll
            for (int j = 0; j < 2; j++)
                pa[j] = *(const float4*)(A + (m0 + ar[j]) * K + k0 + akk[j]);
            #pragma unroll
            for (int j = 0; j < 4; j++)
                pb[j] = *(const float4*)(Bt + (n0 + br[j]) * K + k0 + bkk[j]);
        }

        // ---- compute on buffer bs
        const float* As = sm + bs * BUF_FLOATS;
        const float* Bs = As + ABUF_FLOATS;
        #pragma unroll
        for (int ks = 0; ks < 2; ks++) {
            uint32_t af[4][4];
            #pragma unroll
            for (int mi = 0; mi < 4; mi++) {
                const uint32_t* ap = (const uint32_t*)(As +
                    (warp_m * 64 + mi * 16 + g) * APITCH + ks * 8 + c);
                af[mi][0] = ap[0];
                af[mi][1] = ap[8 * APITCH];
                af[mi][2] = ap[4];
                af[mi][3] = ap[8 * APITCH + 4];
            }
            uint32_t bf[8][2];
            #pragma unroll
            for (int ni = 0; ni < 8; ni++) {
                const uint32_t* bp = (const uint32_t*)(Bs +
                    (warp_n * 64 + ni * 8 + g) * APITCH + ks * 8 + c);
                bf[ni][0] = bp[0];
                bf[ni][1] = bp[4];
            }
            #pragma unroll
            for (int mi = 0; mi < 4; mi++)
                #pragma unroll
                for (int ni = 0; ni < 8; ni++)
                    mma_tf32(acc[mi][ni], af[mi], bf[ni]);
        }

        // ---- store next tile into the other buffer
        if (more) {
            float* Asn = sm + (bs ^ 1) * BUF_FLOATS;
            float* Bsn = Asn + ABUF_FLOATS;
            #pragma unroll
            for (int j = 0; j < 2; j++) {
                uint32_t* p = (uint32_t*)(Asn + ar[j] * APITCH + akk[j]);
                p[0] = f2tf(pa[j].x); p[1] = f2tf(pa[j].y);
                p[2] = f2tf(pa[j].z); p[3] = f2tf(pa[j].w);
            }
            #pragma unroll
            for (int j = 0; j < 4; j++) {
                uint32_t* p = (uint32_t*)(Bsn + br[j] * APITCH + bkk[j]);
                p[0] = f2tf(pb[j].x); p[1] = f2tf(pb[j].y);
                p[2] = f2tf(pb[j].z); p[3] = f2tf(pb[j].w);
            }
            __syncthreads();
        }
    }

    // ---- epilogue: direct float2 stores (full 32B sectors)
    #pragma unroll
    for (int mi = 0; mi < 4; mi++) {
        const size_t row0 = m0 + warp_m * 64 + mi * 16 + g;
        #pragma unroll
        for (int ni = 0; ni < 8; ni++) {
            const size_t col = n0 + warp_n * 64 + ni * 8 + 2 * c;
            *(float2*)(Cm + row0 * N + col) =
                make_float2(acc[mi][ni][0], acc[mi][ni][1]);
            *(float2*)(Cm + (row0 + 8) * N + col) =
                make_float2(acc[mi][ni][2], acc[mi][ni][3]);
        }
    }
}

// ---------------- transpose: out[n][k] = in[k][n]; in [R x Cc] -----------------
__global__ __launch_bounds__(256) void transpose_kernel(
    const float* __restrict__ in, float* __restrict__ out, int R, int Cc)
{
    __shared__ float tile[32][33];
    int c0 = blockIdx.x * 32, r0 = blockIdx.y * 32;
    int tx = threadIdx.x & 31, ty = threadIdx.x >> 5;   // 32 x 8
    #pragma unroll
    for (int j = 0; j < 4; j++)
        tile[ty + j * 8][tx] = in[(size_t)(r0 + ty + j * 8) * Cc + c0 + tx];
    __syncthreads();
    #pragma unroll
    for (int j = 0; j < 4; j++)
        out[(size_t)(c0 + ty + j * 8) * R + r0 + tx] = tile[tx][ty + j * 8];
}

// ---------------- RoPE + transpose: qkv[B,T,3C] -> q/k/v [B,H,T,HD] ------------
__global__ __launch_bounds__(256) void rope_kernel(
    const float* __restrict__ qkv, const float* __restrict__ rope,
    float* __restrict__ q, float* __restrict__ k, float* __restrict__ v)
{
    int idx = blockIdx.x * 256 + threadIdx.x;   // B*T*H*(HD/2)
    int p = idx & 63;
    int h = (idx >> 6) & 15;
    int t = (idx >> 10) & 2047;
    int b = idx >> 21;

    float2 cs = ((const float2*)rope)[t * 64 + p];
    size_t base_in = ((size_t)(b * T_ + t)) * (3 * C_) + h * HD_ + p * 2;
    float2 qv = *(const float2*)(qkv + base_in);
    float2 kv = *(const float2*)(qkv + base_in + C_);
    float2 vv = *(const float2*)(qkv + base_in + 2 * C_);

    float2 qo = make_float2(qv.x * cs.x - qv.y * cs.y, qv.y * cs.x + qv.x * cs.y);
    float2 ko = make_float2(kv.x * cs.x - kv.y * cs.y, kv.y * cs.x + kv.x * cs.y);

    size_t base_out = ((size_t)((b * H_ + h) * T_ + t)) * HD_ + p * 2;
    *(float2*)(q + base_out) = qo;
    *(float2*)(k + base_out) = ko;
    *(float2*)(v + base_out) = vv;
}

// ---------------- Flash attention (fp32, causal), 64x64 tiles ------------------
__global__ __launch_bounds__(256) void attn_kernel(
    const float* __restrict__ Qg_, const float* __restrict__ Kg_,
    const float* __restrict__ Vg_, float* __restrict__ Y)
{
    extern __shared__ float smn[];
    float* Qs = smn;              // 64*128
    float* Ks = Qs + 64 * 128;    // 64*128, XOR-swizzled float4 chunks
    float* Vs = Ks + 64 * 128;    // 64*128
    float* Ss = Vs + 64 * 128;    // 64*64 (P tile)

    const int qt = blockIdx.x;
    const int bh = blockIdx.y;
    const int b  = bh >> 4, h = bh & 15;
    const int tid = threadIdx.x;
    const int tx = tid & 15, ty = tid >> 4;
    const float scale = 0.08838834764831845f;   // 1/sqrt(128)

    const size_t head_off = (size_t)bh * T_ * HD_;
    const float4* Qg = (const float4*)(Qg_ + head_off + (size_t)qt * 64 * HD_);

    for (int i = tid; i < 64 * HD_ / 4; i += 256) {
        float4 v = Qg[i];
        v.x *= scale; v.y *= scale; v.z *= scale; v.w *= scale;
        ((float4*)Qs)[i] = v;
    }

    float m[4], l[4], o[4][8];
    #pragma unroll
    for (int i = 0; i < 4; i++) {
        m[i] = -1e30f; l[i] = 0.f;
        #pragma unroll
        for (int cq = 0; cq < 8; cq++) o[i][cq] = 0.f;
    }

    const int sw = tx & 7;

    for (int kt = 0; kt <= qt; kt++) {
        __syncthreads();
        const float4* Kg = (const float4*)(Kg_ + head_off + (size_t)kt * 64 * HD_);
        const float4* Vg = (const float4*)(Vg_ + head_off + (size_t)kt * 64 * HD_);
        for (int i = tid; i < 2048; i += 256) {
            int cc = i >> 5, d4 = i & 31;
            ((float4*)Ks)[cc * 32 + (d4 ^ ((cc >> 2) & 7))] = Kg[i];
            ((float4*)Vs)[i] = Vg[i];
        }
        __syncthreads();

        float s[4][4];
        #pragma unroll
        for (int i = 0; i < 4; i++)
            #pragma unroll
            for (int j = 0; j < 4; j++) s[i][j] = 0.f;

        #pragma unroll 4
        for (int d4 = 0; d4 < 32; d4++) {
            float4 q4[4], k4[4];
            #pragma unroll
            for (int i = 0; i < 4; i++)
                q4[i] = ((const float4*)Qs)[(ty * 4 + i) * 32 + d4];
            #pragma unroll
            for (int j = 0; j < 4; j++)
                k4[j] = ((const float4*)Ks)[(tx * 4 + j) * 32 + (d4 ^ sw)];
            #pragma unroll
            for (int i = 0; i < 4; i++)
                #pragma unroll
                for (int j = 0; j < 4; j++) {
                    s[i][j] += q4[i].x * k4[j].x;
                    s[i][j] += q4[i].y * k4[j].y;
                    s[i][j] += q4[i].z * k4[j].z;
                    s[i][j] += q4[i].w * k4[j].w;
                }
        }

        if (kt == qt) {
            #pragma unroll
            for (int i = 0; i < 4; i++)
                #pragma unroll
                for (int j = 0; j < 4; j++)
                    if (tx * 4 + j > ty * 4 + i) s[i][j] = -1e30f;
        }

        #pragma unroll
        for (int i = 0; i < 4; i++) {
            float rm = fmaxf(fmaxf(s[i][0], s[i][1]), fmaxf(s[i][2], s[i][3]));
            #pragma unroll
            for (int off = 8; off; off >>= 1)
                rm = fmaxf(rm, __shfl_xor_sync(0xffffffffu, rm, off));
            float mn = fmaxf(m[i], rm);
            float corr = __expf(m[i] - mn);
            m[i] = mn;
            float rs = 0.f;
            #pragma unroll
            for (int j = 0; j < 4; j++) { s[i][j] = __expf(s[i][j] - mn); rs += s[i][j]; }
            #pragma unroll
            for (int off = 8; off; off >>= 1)
                rs += __shfl_xor_sync(0xffffffffu, rs, off);
            l[i] = l[i] * corr + rs;
            #pragma unroll
            for (int cq = 0; cq < 8; cq++) o[i][cq] *= corr;
            *(float4*)&Ss[(ty * 4 + i) * 64 + tx * 4] =
                make_float4(s[i][0], s[i][1], s[i][2], s[i][3]);
        }
        __syncthreads();

        #pragma unroll 4
        for (int kk = 0; kk < 64; kk++) {
            float p0 = Ss[(ty * 4 + 0) * 64 + kk];
            float p1 = Ss[(ty * 4 + 1) * 64 + kk];
            float p2 = Ss[(ty * 4 + 2) * 64 + kk];
            float p3 = Ss[(ty * 4 + 3) * 64 + kk];
            float4 v0 = ((const float4*)Vs)[kk * 32 + tx];
            float4 v1 = ((const float4*)Vs)[kk * 32 + 16 + tx];
            float p[4] = {p0, p1, p2, p3};
            #pragma unroll
            for (int i = 0; i < 4; i++) {
                o[i][0] += p[i] * v0.x; o[i][1] += p[i] * v0.y;
                o[i][2] += p[i] * v0.z; o[i][3] += p[i] * v0.w;
                o[i][4] += p[i] * v1.x; o[i][5] += p[i] * v1.y;
                o[i][6] += p[i] * v1.z; o[i][7] += p[i] * v1.w;
            }
        }
    }

    float* Yb = Y + ((size_t)(b * T_ + qt * 64)) * C_ + h * HD_;
    #pragma unroll
    for (int i = 0; i < 4; i++) {
        float inv = 1.f / l[i];
        size_t row = (size_t)(ty * 4 + i) * C_;
        float4 v0 = make_float4(o[i][0]*inv, o[i][1]*inv, o[i][2]*inv, o[i][3]*inv);
        float4 v1 = make_float4(o[i][4]*inv, o[i][5]*inv, o[i][6]*inv, o[i][7]*inv);
        *(float4*)(Yb + row + tx * 4)      = v0;
        *(float4*)(Yb + row + 64 + tx * 4) = v1;
    }
}

// ---------------- launch --------------------------------------------------------
extern "C" void kernel_launch(void* const* d_in, const int* in_sizes, int n_in,
                              void* d_out, int out_size)
{
    const float* x     = (const float*)d_in[0];
    const float* rope  = (const float*)d_in[1];
    const float* Wqkv  = (const float*)d_in[2];
    const float* Wproj = (const float*)d_in[3];
    float* out = (float*)d_out;

    float *qkv, *q, *k, *v, *y, *wqkvT, *wprojT;
    cudaGetSymbolAddress((void**)&qkv,    g_qkv);
    cudaGetSymbolAddress((void**)&q,      g_q);
    cudaGetSymbolAddress((void**)&k,      g_k);
    cudaGetSymbolAddress((void**)&v,      g_v);
    cudaGetSymbolAddress((void**)&y,      g_y);
    cudaGetSymbolAddress((void**)&wqkvT,  g_wqkvT);
    cudaGetSymbolAddress((void**)&wprojT, g_wprojT);

    cudaFuncSetAttribute(gemm_tf32, cudaFuncAttributeMaxDynamicSharedMemorySize,
                         GSM_BYTES);
    cudaFuncSetAttribute(attn_kernel, cudaFuncAttributeMaxDynamicSharedMemorySize,
                         (3 * 64 * 128 + 64 * 64) * 4);

    // 0) transpose weights to K-major for the mma GEMM (B operand is .col)
    transpose_kernel<<<dim3((3 * C_) / 32, C_ / 32), 256>>>(Wqkv, wqkvT, C_, 3 * C_);
    transpose_kernel<<<dim3(C_ / 32, C_ / 32), 256>>>(Wproj, wprojT, C_, C_);

    // 1) qkv = x @ Wqkv   (M=8192, N=6144, K=2048)
    gemm_tf32<<<dim3((B_ * T_) / 128, (3 * C_) / 256), 256, GSM_BYTES>>>(
        x, wqkvT, qkv, B_ * T_, 3 * C_, C_);

    // 2) RoPE + transpose to [B,H,T,HD]
    rope_kernel<<<(B_ * T_ * H_ * (HD_ / 2)) / 256, 256>>>(qkv, rope, q, k, v);

    // 3) causal flash attention -> y [B,T,C]
    const int smem_bytes = (3 * 64 * 128 + 64 * 64) * 4;
    attn_kernel<<<dim3(T_ / 64, B_ * H_), 256, smem_bytes>>>(q, k, v, y);

    // 4) out = y @ Wproj  (M=8192, N=2048, K=2048)
    gemm_tf32<<<dim3((B_ * T_) / 128, C_ / 256), 256, GSM_BYTES>>>(
        y, wprojT, out, B_ * T_, C_, C_);
}

// round 5
// speedup vs baseline: 2.0689x; 1.0565x over previous
#include <cuda_runtime.h>
#include <cstdint>
#include <cstddef>

#define B_  4
#define T_  2048
#define C_  2048
#define H_  16
#define HD_ 128

// ---------------- scratch (static __device__ — no allocations allowed) ----------
__device__ float g_qkv[(size_t)B_ * T_ * 3 * C_];          // [B*T, 3C]
__device__ float g_q[(size_t)B_ * H_ * T_ * HD_];          // [B,H,T,HD]
__device__ float g_k[(size_t)B_ * H_ * T_ * HD_];
__device__ float g_v[(size_t)B_ * H_ * T_ * HD_];
__device__ float g_y[(size_t)B_ * T_ * C_];                // attention out (tf32-rounded)
__device__ float g_xtf[(size_t)B_ * T_ * C_];              // x rounded to tf32
__device__ float g_wqkvT[(size_t)3 * C_ * C_];             // Wqkv^T  [3C, C] (tf32)
__device__ float g_wprojT[(size_t)C_ * C_];                // Wproj^T [C, C] (tf32)

// ---------------- small helpers -------------------------------------------------
__device__ __forceinline__ uint32_t f2tf(float x) {
    uint32_t u;
    asm("cvt.rna.tf32.f32 %0, %1;" : "=r"(u) : "f"(x));
    return u;
}
__device__ __forceinline__ float f2tf_f(float x) { return __uint_as_float(f2tf(x)); }

__device__ __forceinline__ void mma_tf32(float* d, const uint32_t* a,
                                         const uint32_t* b) {
    asm volatile(
        "mma.sync.aligned.m16n8k8.row.col.f32.tf32.tf32.f32 "
        "{%0,%1,%2,%3}, {%4,%5,%6,%7}, {%8,%9}, {%0,%1,%2,%3};"
        : "+f"(d[0]), "+f"(d[1]), "+f"(d[2]), "+f"(d[3])
        : "r"(a[0]), "r"(a[1]), "r"(a[2]), "r"(a[3]), "r"(b[0]), "r"(b[1]));
}
__device__ __forceinline__ uint32_t smem_u32(const void* p) {
    uint32_t a;
    asm("{ .reg .u64 t; cvta.to.shared.u64 t, %1; cvt.u32.u64 %0, t; }"
        : "=r"(a) : "l"(p));
    return a;
}
__device__ __forceinline__ void cp16(uint32_t dst, const void* src) {
    asm volatile("cp.async.cg.shared.global [%0], [%1], 16;"
                 :: "r"(dst), "l"(src) : "memory");
}
__device__ __forceinline__ void cp_commit() {
    asm volatile("cp.async.commit_group;" ::: "memory");
}
template <int N>
__device__ __forceinline__ void cp_wait() {
    asm volatile("cp.async.wait_group %0;" :: "n"(N) : "memory");
}

// ===================== TF32 mma.sync GEMM (cp.async 4-stage) ====================
// C[M,N] = A[M,K] * Bt[N,K]^T ; A,Bt already tf32-rounded fp32, K-major both.
// CTA tile 128x256, BK=16, 256 threads = 8 warps (2 M x 4 N), warp tile 64x64.
// Smem rows padded to 20 floats (80B, 16B-aligned) -> conflict-free frag loads.
#define APITCH 20
#define ABUF_FLOATS (128 * APITCH)               // 2560
#define BBUF_FLOATS (256 * APITCH)               // 5120
#define BUF_FLOATS  (ABUF_FLOATS + BBUF_FLOATS)  // 7680
#define STAGES 4
#define GSM_BYTES (STAGES * BUF_FLOATS * 4)      // 122880

__global__ __launch_bounds__(256, 1) void gemm_tf32(
    const float* __restrict__ A, const float* __restrict__ Bt,
    float* __restrict__ Cm, int M, int N, int K)
{
    extern __shared__ float sm[];
    const uint32_t sbase = smem_u32(sm);
    const int tid  = threadIdx.x;
    const int wid  = tid >> 5;
    const int lane = tid & 31;
    const int g    = lane >> 2;      // groupID 0..7
    const int c    = lane & 3;       // threadID_in_group 0..3
    const int warp_m = wid & 1;      // 0..1  (64 rows each)
    const int warp_n = wid >> 1;     // 0..3  (64 cols each)

    const size_t m0 = (size_t)blockIdx.x * 128;
    const size_t n0 = (size_t)blockIdx.y * 256;

    // per-thread copy coordinates (A: 512 x 16B, B: 1024 x 16B)
    const int ar[2]  = { (tid + 0)   >> 2, (tid + 256) >> 2 };
    const int akk[2] = { ((tid + 0)   & 3) << 2, ((tid + 256) & 3) << 2 };
    int br[4], bkk[4];
    #pragma unroll
    for (int j = 0; j < 4; j++) {
        br[j]  = (tid + j * 256) >> 2;
        bkk[j] = ((tid + j * 256) & 3) << 2;
    }

    float acc[4][8][4];
    #pragma unroll
    for (int mi = 0; mi < 4; mi++)
        #pragma unroll
        for (int ni = 0; ni < 8; ni++)
            #pragma unroll
            for (int q = 0; q < 4; q++) acc[mi][ni][q] = 0.f;

    const int niter = K >> 4;    // BK = 16

    // issue copies for stage `it` (caller guards it < niter)
    auto issue = [&](int it) {
        const int k0 = it << 4;
        const uint32_t As = sbase + (uint32_t)(it & (STAGES - 1)) * (BUF_FLOATS * 4);
        const uint32_t Bs = As + ABUF_FLOATS * 4;
        #pragma unroll
        for (int j = 0; j < 2; j++)
            cp16(As + (ar[j] * APITCH + akk[j]) * 4,
                 A + (m0 + ar[j]) * K + k0 + akk[j]);
        #pragma unroll
        for (int j = 0; j < 4; j++)
            cp16(Bs + (br[j] * APITCH + bkk[j]) * 4,
                 Bt + (n0 + br[j]) * K + k0 + bkk[j]);
    };

    // prologue: stages 0..2
    #pragma unroll
    for (int s = 0; s < STAGES - 1; s++) {
        if (s < niter) issue(s);
        cp_commit();
    }

    for (int it = 0; it < niter; ++it) {
        cp_wait<STAGES - 2>();      // stage `it` complete
        __syncthreads();

        const float* As = sm + (it & (STAGES - 1)) * BUF_FLOATS;
        const float* Bs = As + ABUF_FLOATS;
        #pragma unroll
        for (int ks = 0; ks < 2; ks++) {
            uint32_t af[4][4];
            #pragma unroll
            for (int mi = 0; mi < 4; mi++) {
                const uint32_t* ap = (const uint32_t*)(As +
                    (warp_m * 64 + mi * 16 + g) * APITCH + ks * 8 + c);
                af[mi][0] = ap[0];
                af[mi][1] = ap[8 * APITCH];
                af[mi][2] = ap[4];
                af[mi][3] = ap[8 * APITCH + 4];
            }
            uint32_t bf[8][2];
            #pragma unroll
            for (int ni = 0; ni < 8; ni++) {
                const uint32_t* bp = (const uint32_t*)(Bs +
                    (warp_n * 64 + ni * 8 + g) * APITCH + ks * 8 + c);
                bf[ni][0] = bp[0];
                bf[ni][1] = bp[4];
            }
            #pragma unroll
            for (int mi = 0; mi < 4; mi++)
                #pragma unroll
                for (int ni = 0; ni < 8; ni++)
                    mma_tf32(acc[mi][ni], af[mi], bf[ni]);
        }

        // issue stage it+3 into slot (it-1)&3 (safe: everyone synced above)
        if (it + STAGES - 1 < niter) issue(it + STAGES - 1);
        cp_commit();                // empty group if nothing issued (keeps count)
    }

    // ---- epilogue: direct float2 stores
    #pragma unroll
    for (int mi = 0; mi < 4; mi++) {
        const size_t row0 = m0 + warp_m * 64 + mi * 16 + g;
        #pragma unroll
        for (int ni = 0; ni < 8; ni++) {
            const size_t col = n0 + warp_n * 64 + ni * 8 + 2 * c;
            *(float2*)(Cm + row0 * N + col) =
                make_float2(acc[mi][ni][0], acc[mi][ni][1]);
            *(float2*)(Cm + (row0 + 8) * N + col) =
                make_float2(acc[mi][ni][2], acc[mi][ni][3]);
        }
    }
}

// ---------------- tf32 pre-round: out[i] = rna_tf32(in[i]) ---------------------
__global__ __launch_bounds__(256) void tf32_round_kernel(
    const float* __restrict__ in, float* __restrict__ out)
{
    int i = blockIdx.x * 256 + threadIdx.x;
    float4 v = ((const float4*)in)[i];
    v.x = f2tf_f(v.x); v.y = f2tf_f(v.y);
    v.z = f2tf_f(v.z); v.w = f2tf_f(v.w);
    ((float4*)out)[i] = v;
}

// ---------------- transpose + tf32 round: out[n][k] = tf32(in[k][n]) -----------
__global__ __launch_bounds__(256) void transpose_kernel(
    const float* __restrict__ in, float* __restrict__ out, int R, int Cc)
{
    __shared__ float tile[32][33];
    int c0 = blockIdx.x * 32, r0 = blockIdx.y * 32;
    int tx = threadIdx.x & 31, ty = threadIdx.x >> 5;   // 32 x 8
    #pragma unroll
    for (int j = 0; j < 4; j++)
        tile[ty + j * 8][tx] = in[(size_t)(r0 + ty + j * 8) * Cc + c0 + tx];
    __syncthreads();
    #pragma unroll
    for (int j = 0; j < 4; j++)
        out[(size_t)(c0 + ty + j * 8) * R + r0 + tx] = f2tf_f(tile[tx][ty + j * 8]);
}

// ---------------- RoPE + transpose: qkv[B,T,3C] -> q/k/v [B,H,T,HD] ------------
__global__ __launch_bounds__(256) void rope_kernel(
    const float* __restrict__ qkv, const float* __restrict__ rope,
    float* __restrict__ q, float* __restrict__ k, float* __restrict__ v)
{
    int idx = blockIdx.x * 256 + threadIdx.x;   // B*T*H*(HD/2)
    int p = idx & 63;
    int h = (idx >> 6) & 15;
    int t = (idx >> 10) & 2047;
    int b = idx >> 21;

    float2 cs = ((const float2*)rope)[t * 64 + p];
    size_t base_in = ((size_t)(b * T_ + t)) * (3 * C_) + h * HD_ + p * 2;
    float2 qv = *(const float2*)(qkv + base_in);
    float2 kv = *(const float2*)(qkv + base_in + C_);
    float2 vv = *(const float2*)(qkv + base_in + 2 * C_);

    float2 qo = make_float2(qv.x * cs.x - qv.y * cs.y, qv.y * cs.x + qv.x * cs.y);
    float2 ko = make_float2(kv.x * cs.x - kv.y * cs.y, kv.y * cs.x + kv.x * cs.y);

    size_t base_out = ((size_t)((b * H_ + h) * T_ + t)) * HD_ + p * 2;
    *(float2*)(q + base_out) = qo;
    *(float2*)(k + base_out) = ko;
    *(float2*)(v + base_out) = vv;
}

// ---------------- Flash attention (fp32, causal), 64x64 tiles ------------------
// epilogue writes y pre-rounded to tf32 (it feeds the proj GEMM).
__global__ __launch_bounds__(256) void attn_kernel(
    const float* __restrict__ Qg_, const float* __restrict__ Kg_,
    const float* __restrict__ Vg_, float* __restrict__ Y)
{
    extern __shared__ float smn[];
    float* Qs = smn;              // 64*128
    float* Ks = Qs + 64 * 128;    // 64*128, XOR-swizzled float4 chunks
    float* Vs = Ks + 64 * 128;    // 64*128
    float* Ss = Vs + 64 * 128;    // 64*64 (P tile)

    const int qt = (int)gridDim.x - 1 - (int)blockIdx.x;   // heavy tiles first
    const int bh = blockIdx.y;
    const int b  = bh >> 4, h = bh & 15;
    const int tid = threadIdx.x;
    const int tx = tid & 15, ty = tid >> 4;
    const float scale = 0.08838834764831845f;   // 1/sqrt(128)

    const size_t head_off = (size_t)bh * T_ * HD_;
    const float4* Qg = (const float4*)(Qg_ + head_off + (size_t)qt * 64 * HD_);

    for (int i = tid; i < 64 * HD_ / 4; i += 256) {
        float4 v = Qg[i];
        v.x *= scale; v.y *= scale; v.z *= scale; v.w *= scale;
        ((float4*)Qs)[i] = v;
    }

    float m[4], l[4], o[4][8];
    #pragma unroll
    for (int i = 0; i < 4; i++) {
        m[i] = -1e30f; l[i] = 0.f;
        #pragma unroll
        for (int cq = 0; cq < 8; cq++) o[i][cq] = 0.f;
    }

    const int sw = tx & 7;

    for (int kt = 0; kt <= qt; kt++) {
        __syncthreads();
        const float4* Kg = (const float4*)(Kg_ + head_off + (size_t)kt * 64 * HD_);
        const float4* Vg = (const float4*)(Vg_ + head_off + (size_t)kt * 64 * HD_);
        for (int i = tid; i < 2048; i += 256) {
            int cc = i >> 5, d4 = i & 31;
            ((float4*)Ks)[cc * 32 + (d4 ^ ((cc >> 2) & 7))] = Kg[i];
            ((float4*)Vs)[i] = Vg[i];
        }
        __syncthreads();

        float s[4][4];
        #pragma unroll
        for (int i = 0; i < 4; i++)
            #pragma unroll
            for (int j = 0; j < 4; j++) s[i][j] = 0.f;

        #pragma unroll 4
        for (int d4 = 0; d4 < 32; d4++) {
            float4 q4[4], k4[4];
            #pragma unroll
            for (int i = 0; i < 4; i++)
                q4[i] = ((const float4*)Qs)[(ty * 4 + i) * 32 + d4];
            #pragma unroll
            for (int j = 0; j < 4; j++)
                k4[j] = ((const float4*)Ks)[(tx * 4 + j) * 32 + (d4 ^ sw)];
            #pragma unroll
            for (int i = 0; i < 4; i++)
                #pragma unroll
                for (int j = 0; j < 4; j++) {
                    s[i][j] += q4[i].x * k4[j].x;
                    s[i][j] += q4[i].y * k4[j].y;
                    s[i][j] += q4[i].z * k4[j].z;
                    s[i][j] += q4[i].w * k4[j].w;
                }
        }

        if (kt == qt) {
            #pragma unroll
            for (int i = 0; i < 4; i++)
                #pragma unroll
                for (int j = 0; j < 4; j++)
                    if (tx * 4 + j > ty * 4 + i) s[i][j] = -1e30f;
        }

        #pragma unroll
        for (int i = 0; i < 4; i++) {
            float rm = fmaxf(fmaxf(s[i][0], s[i][1]), fmaxf(s[i][2], s[i][3]));
            #pragma unroll
            for (int off = 8; off; off >>= 1)
                rm = fmaxf(rm, __shfl_xor_sync(0xffffffffu, rm, off));
            float mn = fmaxf(m[i], rm);
            float corr = __expf(m[i] - mn);
            m[i] = mn;
            float rs = 0.f;
            #pragma unroll
            for (int j = 0; j < 4; j++) { s[i][j] = __expf(s[i][j] - mn); rs += s[i][j]; }
            #pragma unroll
            for (int off = 8; off; off >>= 1)
                rs += __shfl_xor_sync(0xffffffffu, rs, off);
            l[i] = l[i] * corr + rs;
            #pragma unroll
            for (int cq = 0; cq < 8; cq++) o[i][cq] *= corr;
            *(float4*)&Ss[(ty * 4 + i) * 64 + tx * 4] =
                make_float4(s[i][0], s[i][1], s[i][2], s[i][3]);
        }
        __syncthreads();

        #pragma unroll 4
        for (int kk = 0; kk < 64; kk++) {
            float p0 = Ss[(ty * 4 + 0) * 64 + kk];
            float p1 = Ss[(ty * 4 + 1) * 64 + kk];
            float p2 = Ss[(ty * 4 + 2) * 64 + kk];
            float p3 = Ss[(ty * 4 + 3) * 64 + kk];
            float4 v0 = ((const float4*)Vs)[kk * 32 + tx];
            float4 v1 = ((const float4*)Vs)[kk * 32 + 16 + tx];
            float p[4] = {p0, p1, p2, p3};
            #pragma unroll
            for (int i = 0; i < 4; i++) {
                o[i][0] += p[i] * v0.x; o[i][1] += p[i] * v0.y;
                o[i][2] += p[i] * v0.z; o[i][3] += p[i] * v0.w;
                o[i][4] += p[i] * v1.x; o[i][5] += p[i] * v1.y;
                o[i][6] += p[i] * v1.z; o[i][7] += p[i] * v1.w;
            }
        }
    }

    float* Yb = Y + ((size_t)(b * T_ + qt * 64)) * C_ + h * HD_;
    #pragma unroll
    for (int i = 0; i < 4; i++) {
        float inv = 1.f / l[i];
        size_t row = (size_t)(ty * 4 + i) * C_;
        float4 v0 = make_float4(f2tf_f(o[i][0]*inv), f2tf_f(o[i][1]*inv),
                                f2tf_f(o[i][2]*inv), f2tf_f(o[i][3]*inv));
        float4 v1 = make_float4(f2tf_f(o[i][4]*inv), f2tf_f(o[i][5]*inv),
                                f2tf_f(o[i][6]*inv), f2tf_f(o[i][7]*inv));
        *(float4*)(Yb + row + tx * 4)      = v0;
        *(float4*)(Yb + row + 64 + tx * 4) = v1;
    }
}

// ---------------- launch --------------------------------------------------------
extern "C" void kernel_launch(void* const* d_in, const int* in_sizes, int n_in,
                              void* d_out, int out_size)
{
    const float* x     = (const float*)d_in[0];
    const float* rope  = (const float*)d_in[1];
    const float* Wqkv  = (const float*)d_in[2];
    const float* Wproj = (const float*)d_in[3];
    float* out = (float*)d_out;

    float *qkv, *q, *k, *v, *y, *xtf, *wqkvT, *wprojT;
    cudaGetSymbolAddress((void**)&qkv,    g_qkv);
    cudaGetSymbolAddress((void**)&q,      g_q);
    cudaGetSymbolAddress((void**)&k,      g_k);
    cudaGetSymbolAddress((void**)&v,      g_v);
    cudaGetSymbolAddress((void**)&y,      g_y);
    cudaGetSymbolAddress((void**)&xtf,    g_xtf);
    cudaGetSymbolAddress((void**)&wqkvT,  g_wqkvT);
    cudaGetSymbolAddress((void**)&wprojT, g_wprojT);

    cudaFuncSetAttribute(gemm_tf32, cudaFuncAttributeMaxDynamicSharedMemorySize,
                         GSM_BYTES);
    cudaFuncSetAttribute(attn_kernel, cudaFuncAttributeMaxDynamicSharedMemorySize,
                         (3 * 64 * 128 + 64 * 64) * 4);

    // 0) operand prep: tf32-rounded x; transposed+rounded weights
    tf32_round_kernel<<<(B_ * T_ * C_ / 4) / 256, 256>>>(x, xtf);
    transpose_kernel<<<dim3((3 * C_) / 32, C_ / 32), 256>>>(Wqkv, wqkvT, C_, 3 * C_);
    transpose_kernel<<<dim3(C_ / 32, C_ / 32), 256>>>(Wproj, wprojT, C_, C_);

    // 1) qkv = x @ Wqkv   (M=8192, N=6144, K=2048)
    gemm_tf32<<<dim3((B_ * T_) / 128, (3 * C_) / 256), 256, GSM_BYTES>>>(
        xtf, wqkvT, qkv, B_ * T_, 3 * C_, C_);

    // 2) RoPE + transpose to [B,H,T,HD]
    rope_kernel<<<(B_ * T_ * H_ * (HD_ / 2)) / 256, 256>>>(qkv, rope, q, k, v);

    // 3) causal flash attention -> y [B,T,C] (y emitted tf32-rounded)
    const int smem_bytes = (3 * 64 * 128 + 64 * 64) * 4;
    attn_kernel<<<dim3(T_ / 64, B_ * H_), 256, smem_bytes>>>(q, k, v, y);

    // 4) out = y @ Wproj  (M=8192, N=2048, K=2048)
    gemm_tf32<<<dim3((B_ * T_) / 128, C_ / 256), 256, GSM_BYTES>>>(
        y, wprojT, out, B_ * T_, C_, C_);
}

// round 8
// speedup vs baseline: 2.8273x; 1.3666x over previous
#include <cuda_runtime.h>
#include <cstdint>
#include <cstddef>

#define B_  4
#define T_  2048
#define C_  2048
#define H_  16
#define HD_ 128

// ---------------- scratch (static __device__ — no allocations allowed) ----------
__device__ float g_qkv[(size_t)B_ * T_ * 3 * C_];          // [B*T, 3C]
__device__ float g_q  [(size_t)B_ * H_ * T_ * HD_];        // [B,H,T,HD] tf32, pre-scaled
__device__ float g_khi[(size_t)B_ * H_ * T_ * HD_];        // K hi (tf32)
__device__ float g_klo[(size_t)B_ * H_ * T_ * HD_];        // K lo (tf32 of residual)
__device__ float g_v  [(size_t)B_ * H_ * T_ * HD_];        // V (tf32-rounded)
__device__ float g_y[(size_t)B_ * T_ * C_];                // attention out (tf32-rounded)
__device__ float g_xtf[(size_t)B_ * T_ * C_];              // x rounded to tf32
__device__ float g_wqkvT[(size_t)3 * C_ * C_];             // Wqkv^T  [3C, C] (tf32)
__device__ float g_wprojT[(size_t)C_ * C_];                // Wproj^T [C, C] (tf32)

// ---------------- small helpers -------------------------------------------------
__device__ __forceinline__ uint32_t f2tf(float x) {
    uint32_t u;
    asm("cvt.rna.tf32.f32 %0, %1;" : "=r"(u) : "f"(x));
    return u;
}
__device__ __forceinline__ float f2tf_f(float x) { return __uint_as_float(f2tf(x)); }

__device__ __forceinline__ void mma_tf32(float* d, const uint32_t* a,
                                         const uint32_t* b) {
    asm volatile(
        "mma.sync.aligned.m16n8k8.row.col.f32.tf32.tf32.f32 "
        "{%0,%1,%2,%3}, {%4,%5,%6,%7}, {%8,%9}, {%0,%1,%2,%3};"
        : "+f"(d[0]), "+f"(d[1]), "+f"(d[2]), "+f"(d[3])
        : "r"(a[0]), "r"(a[1]), "r"(a[2]), "r"(a[3]), "r"(b[0]), "r"(b[1]));
}
__device__ __forceinline__ uint32_t smem_u32(const void* p) {
    uint32_t a;
    asm("{ .reg .u64 t; cvta.to.shared.u64 t, %1; cvt.u32.u64 %0, t; }"
        : "=r"(a) : "l"(p));
    return a;
}
__device__ __forceinline__ void cp16(uint32_t dst, const void* src) {
    asm volatile("cp.async.cg.shared.global [%0], [%1], 16;"
                 :: "r"(dst), "l"(src) : "memory");
}
__device__ __forceinline__ void cp_commit() {
    asm volatile("cp.async.commit_group;" ::: "memory");
}
template <int N>
__device__ __forceinline__ void cp_wait() {
    asm volatile("cp.async.wait_group %0;" :: "n"(N) : "memory");
}
// FFMA-pipe exp (keeps MUFU free; poly rel err ~2e-6)
__device__ __forceinline__ float expf_fast(float x) {
    float y = fmaxf(x, -60.f) * 1.4426950408889634f;
    float nf;
    asm("cvt.rni.f32.f32 %0, %1;" : "=f"(nf) : "f"(y));
    float f = y - nf;
    float p =              1.3333558e-3f;
    p = fmaf(p, f, 9.6181291e-3f);
    p = fmaf(p, f, 5.5504109e-2f);
    p = fmaf(p, f, 2.4022651e-1f);
    p = fmaf(p, f, 6.9314718e-1f);
    p = fmaf(p, f, 1.0f);
    return __int_as_float(__float_as_int(p) + (((int)nf) << 23));
}

// ===================== TF32 mma.sync GEMM (cp.async 4-stage) ====================
#define APITCH 20
#define ABUF_FLOATS (128 * APITCH)
#define BBUF_FLOATS (256 * APITCH)
#define BUF_FLOATS  (ABUF_FLOATS + BBUF_FLOATS)
#define STAGES 4
#define GSM_BYTES (STAGES * BUF_FLOATS * 4)

__global__ __launch_bounds__(256, 1) void gemm_tf32(
    const float* __restrict__ A, const float* __restrict__ Bt,
    float* __restrict__ Cm, int M, int N, int K)
{
    extern __shared__ float sm[];
    const uint32_t sbase = smem_u32(sm);
    const int tid  = threadIdx.x;
    const int wid  = tid >> 5;
    const int lane = tid & 31;
    const int g    = lane >> 2;
    const int c    = lane & 3;
    const int warp_m = wid & 1;
    const int warp_n = wid >> 1;

    const size_t m0 = (size_t)blockIdx.x * 128;
    const size_t n0 = (size_t)blockIdx.y * 256;

    const int ar[2]  = { (tid + 0)   >> 2, (tid + 256) >> 2 };
    const int akk[2] = { ((tid + 0)   & 3) << 2, ((tid + 256) & 3) << 2 };
    int br[4], bkk[4];
    #pragma unroll
    for (int j = 0; j < 4; j++) {
        br[j]  = (tid + j * 256) >> 2;
        bkk[j] = ((tid + j * 256) & 3) << 2;
    }

    float acc[4][8][4];
    #pragma unroll
    for (int mi = 0; mi < 4; mi++)
        #pragma unroll
        for (int ni = 0; ni < 8; ni++)
            #pragma unroll
            for (int q = 0; q < 4; q++) acc[mi][ni][q] = 0.f;

    const int niter = K >> 4;

    auto issue = [&](int it) {
        const int k0 = it << 4;
        const uint32_t As = sbase + (uint32_t)(it & (STAGES - 1)) * (BUF_FLOATS * 4);
        const uint32_t Bs = As + ABUF_FLOATS * 4;
        #pragma unroll
        for (int j = 0; j < 2; j++)
            cp16(As + (ar[j] * APITCH + akk[j]) * 4,
                 A + (m0 + ar[j]) * K + k0 + akk[j]);
        #pragma unroll
        for (int j = 0; j < 4; j++)
            cp16(Bs + (br[j] * APITCH + bkk[j]) * 4,
                 Bt + (n0 + br[j]) * K + k0 + bkk[j]);
    };

    #pragma unroll
    for (int s = 0; s < STAGES - 1; s++) {
        if (s < niter) issue(s);
        cp_commit();
    }

    for (int it = 0; it < niter; ++it) {
        cp_wait<STAGES - 2>();
        __syncthreads();

        const float* As = sm + (it & (STAGES - 1)) * BUF_FLOATS;
        const float* Bs = As + ABUF_FLOATS;
        #pragma unroll
        for (int ks = 0; ks < 2; ks++) {
            uint32_t af[4][4];
            #pragma unroll
            for (int mi = 0; mi < 4; mi++) {
                const uint32_t* ap = (const uint32_t*)(As +
                    (warp_m * 64 + mi * 16 + g) * APITCH + ks * 8 + c);
                af[mi][0] = ap[0];
                af[mi][1] = ap[8 * APITCH];
                af[mi][2] = ap[4];
                af[mi][3] = ap[8 * APITCH + 4];
            }
            uint32_t bf[8][2];
            #pragma unroll
            for (int ni = 0; ni < 8; ni++) {
                const uint32_t* bp = (const uint32_t*)(Bs +
                    (warp_n * 64 + ni * 8 + g) * APITCH + ks * 8 + c);
                bf[ni][0] = bp[0];
                bf[ni][1] = bp[4];
            }
            #pragma unroll
            for (int mi = 0; mi < 4; mi++)
                #pragma unroll
                for (int ni = 0; ni < 8; ni++)
                    mma_tf32(acc[mi][ni], af[mi], bf[ni]);
        }

        if (it + STAGES - 1 < niter) issue(it + STAGES - 1);
        cp_commit();
    }

    #pragma unroll
    for (int mi = 0; mi < 4; mi++) {
        const size_t row0 = m0 + warp_m * 64 + mi * 16 + g;
        #pragma unroll
        for (int ni = 0; ni < 8; ni++) {
            const size_t col = n0 + warp_n * 64 + ni * 8 + 2 * c;
            *(float2*)(Cm + row0 * N + col) =
                make_float2(acc[mi][ni][0], acc[mi][ni][1]);
            *(float2*)(Cm + (row0 + 8) * N + col) =
                make_float2(acc[mi][ni][2], acc[mi][ni][3]);
        }
    }
}

// ---------------- tf32 pre-round ------------------------------------------------
__global__ __launch_bounds__(256) void tf32_round_kernel(
    const float* __restrict__ in, float* __restrict__ out)
{
    int i = blockIdx.x * 256 + threadIdx.x;
    float4 v = ((const float4*)in)[i];
    v.x = f2tf_f(v.x); v.y = f2tf_f(v.y);
    v.z = f2tf_f(v.z); v.w = f2tf_f(v.w);
    ((float4*)out)[i] = v;
}

// ---------------- transpose + tf32 round ---------------------------------------
__global__ __launch_bounds__(256) void transpose_kernel(
    const float* __restrict__ in, float* __restrict__ out, int R, int Cc)
{
    __shared__ float tile[32][33];
    int c0 = blockIdx.x * 32, r0 = blockIdx.y * 32;
    int tx = threadIdx.x & 31, ty = threadIdx.x >> 5;
    #pragma unroll
    for (int j = 0; j < 4; j++)
        tile[ty + j * 8][tx] = in[(size_t)(r0 + ty + j * 8) * Cc + c0 + tx];
    __syncthreads();
    #pragma unroll
    for (int j = 0; j < 4; j++)
        out[(size_t)(c0 + ty + j * 8) * R + r0 + tx] = f2tf_f(tile[tx][ty + j * 8]);
}

// ---------------- RoPE: qkv -> q(scaled,tf32), khi, klo, v(tf32) ----------------
__global__ __launch_bounds__(256) void rope_kernel(
    const float* __restrict__ qkv, const float* __restrict__ rope,
    float* __restrict__ q, float* __restrict__ khi,
    float* __restrict__ klo, float* __restrict__ v)
{
    int idx = blockIdx.x * 256 + threadIdx.x;
    int p = idx & 63;
    int h = (idx >> 6) & 15;
    int t = (idx >> 10) & 2047;
    int b = idx >> 21;
    const float scale = 0.08838834764831845f;   // 1/sqrt(128)

    float2 cs = ((const float2*)rope)[t * 64 + p];
    size_t base_in = ((size_t)(b * T_ + t)) * (3 * C_) + h * HD_ + p * 2;
    float2 qv = *(const float2*)(qkv + base_in);
    float2 kv = *(const float2*)(qkv + base_in + C_);
    float2 vv = *(const float2*)(qkv + base_in + 2 * C_);

    float2 qo = make_float2((qv.x * cs.x - qv.y * cs.y) * scale,
                            (qv.y * cs.x + qv.x * cs.y) * scale);
    float2 ko = make_float2(kv.x * cs.x - kv.y * cs.y, kv.y * cs.x + kv.x * cs.y);

    float2 qr  = make_float2(f2tf_f(qo.x), f2tf_f(qo.y));
    float2 khv = make_float2(f2tf_f(ko.x), f2tf_f(ko.y));
    float2 klv = make_float2(f2tf_f(ko.x - khv.x), f2tf_f(ko.y - khv.y));
    float2 vr  = make_float2(f2tf_f(vv.x), f2tf_f(vv.y));

    size_t base_out = ((size_t)((b * H_ + h) * T_ + t)) * HD_ + p * 2;
    *(float2*)(q   + base_out) = qr;
    *(float2*)(khi + base_out) = khv;
    *(float2*)(klo + base_out) = klv;
    *(float2*)(v   + base_out) = vr;
}

// ================== Tensor-core flash attention (tf32, causal) ==================
// CTA: 128 q-rows, 8 warps x 16 rows, 256 threads. kt tiles of 32 keys.
// QK^T = Q*Khi + Q*Klo (split-K precision). PV single tf32 MMA.
// Smem: 3-stage KV pipeline, each stage {Khi,Klo,V} 32x128 @ pitch 132.
#define KV_TILE_F   (32 * 132)                  // 4224 floats
#define KV_STRIDE_F (3 * KV_TILE_F)             // 12672 floats per stage
#define ASM_BYTES   (3 * KV_STRIDE_F * 4)       // 152064 bytes

__global__ __launch_bounds__(256, 1) void attn_tc(
    const float* __restrict__ Qg, const float* __restrict__ Khig,
    const float* __restrict__ Klog, const float* __restrict__ Vg,
    float* __restrict__ Y)
{
    extern __shared__ float smn[];
    const uint32_t sbase = smem_u32(smn);
    const int qt = (int)gridDim.x - 1 - (int)blockIdx.x;   // heavy tiles first
    const int bh = blockIdx.y;
    const int b = bh >> 4, h = bh & 15;
    const int tid = threadIdx.x;
    const int w = tid >> 5, lane = tid & 31, g = lane >> 2, c = lane & 3;
    const size_t head = (size_t)bh * T_ * HD_;

    // ---- stage Q tile (already tf32+scaled) into smem pitch 132, extract frags
    {
        const float4* Qt = (const float4*)(Qg + head + (size_t)qt * 128 * HD_);
        for (int i = tid; i < 128 * 32; i += 256) {
            int r = i >> 5, d4 = (i & 31) << 2;
            float4 qv = Qt[i];
            float* dst = smn + r * 132 + d4;
            dst[0] = qv.x; dst[1] = qv.y; dst[2] = qv.z; dst[3] = qv.w;
        }
    }
    __syncthreads();
    uint32_t qf[16][4];
    {
        const float* q0 = smn + (w * 16 + g) * 132 + c;
        #pragma unroll
        for (int ks = 0; ks < 16; ks++) {
            qf[ks][0] = __float_as_uint(q0[ks * 8]);
            qf[ks][1] = __float_as_uint(q0[ks * 8 + 8 * 132]);
            qf[ks][2] = __float_as_uint(q0[ks * 8 + 4]);
            qf[ks][3] = __float_as_uint(q0[ks * 8 + 8 * 132 + 4]);
        }
    }
    __syncthreads();

    float oacc[16][4];
    #pragma unroll
    for (int i = 0; i < 16; i++) {
        oacc[i][0] = 0.f; oacc[i][1] = 0.f; oacc[i][2] = 0.f; oacc[i][3] = 0.f;
    }
    float m0v = -1e30f, m1v = -1e30f, l0 = 0.f, l1 = 0.f;

    const int nkt = qt * 4 + 4;
    const int cr = tid >> 3;              // copy row 0..31
    const int cc = (tid & 7) << 2;        // copy col base (floats)

    // FIXED: each thread copies 4 chunks of 32 floats per row per array,
    // covering the full 32x128 tile (round-7 bug: only dims 0..31 were loaded).
    auto kvissue = [&](int kt) {
        uint32_t dstb = sbase + (uint32_t)(kt % 3) * (KV_STRIDE_F * 4)
                      + cr * (132 * 4);
        size_t srcb = head + ((size_t)kt * 32 + cr) * HD_;
        #pragma unroll
        for (int ch = 0; ch < 4; ch++) {
            uint32_t dst = dstb + (cc + ch * 32) * 4;
            size_t src = srcb + cc + ch * 32;
            cp16(dst,                     Khig + src);
            cp16(dst + KV_TILE_F * 4,     Klog + src);
            cp16(dst + 2 * KV_TILE_F * 4, Vg + src);
        }
    };
    kvissue(0); cp_commit();
    if (nkt > 1) kvissue(1);
    cp_commit();

    const int rg0 = qt * 128 + w * 16 + g;
    const int rg8 = rg0 + 8;

    for (int kt = 0; kt < nkt; kt++) {
        cp_wait<1>();
        __syncthreads();
        const float* Khs = smn + (kt % 3) * KV_STRIDE_F;
        const float* Kls = Khs + KV_TILE_F;
        const float* Vs  = Khs + 2 * KV_TILE_F;

        // ---- S = Q*Khi + Q*Klo  (16x32 per warp)
        float sacc[4][4];
        #pragma unroll
        for (int nt = 0; nt < 4; nt++) {
            sacc[nt][0] = 0.f; sacc[nt][1] = 0.f;
            sacc[nt][2] = 0.f; sacc[nt][3] = 0.f;
        }
        #pragma unroll
        for (int ks = 0; ks < 16; ks++) {
            #pragma unroll
            for (int nt = 0; nt < 4; nt++) {
                const float* kp = Khs + (nt * 8 + g) * 132 + ks * 8 + c;
                uint32_t bh2[2] = { __float_as_uint(kp[0]),
                                    __float_as_uint(kp[4]) };
                mma_tf32(sacc[nt], qf[ks], bh2);
                const float* lp = Kls + (nt * 8 + g) * 132 + ks * 8 + c;
                uint32_t bl2[2] = { __float_as_uint(lp[0]),
                                    __float_as_uint(lp[4]) };
                mma_tf32(sacc[nt], qf[ks], bl2);
            }
        }

        // ---- causal mask (only when tile can cross the diagonal for this warp)
        if (kt * 32 + 31 > qt * 128 + w * 16) {
            #pragma unroll
            for (int nt = 0; nt < 4; nt++) {
                int col = kt * 32 + nt * 8 + 2 * c;
                if (col     > rg0) sacc[nt][0] = -1e30f;
                if (col + 1 > rg0) sacc[nt][1] = -1e30f;
                if (col     > rg8) sacc[nt][2] = -1e30f;
                if (col + 1 > rg8) sacc[nt][3] = -1e30f;
            }
        }

        // ---- online softmax (rows g, g+8; reduce over quad lanes)
        float mx0 = -1e30f, mx1 = -1e30f;
        #pragma unroll
        for (int nt = 0; nt < 4; nt++) {
            mx0 = fmaxf(mx0, fmaxf(sacc[nt][0], sacc[nt][1]));
            mx1 = fmaxf(mx1, fmaxf(sacc[nt][2], sacc[nt][3]));
        }
        mx0 = fmaxf(mx0, __shfl_xor_sync(0xffffffffu, mx0, 1));
        mx0 = fmaxf(mx0, __shfl_xor_sync(0xffffffffu, mx0, 2));
        mx1 = fmaxf(mx1, __shfl_xor_sync(0xffffffffu, mx1, 1));
        mx1 = fmaxf(mx1, __shfl_xor_sync(0xffffffffu, mx1, 2));
        float nm0 = fmaxf(m0v, mx0), nm1 = fmaxf(m1v, mx1);
        float cf0 = expf_fast(m0v - nm0), cf1 = expf_fast(m1v - nm1);
        m0v = nm0; m1v = nm1;

        uint32_t pt[4][4];
        float rs0 = 0.f, rs1 = 0.f;
        #pragma unroll
        for (int nt = 0; nt < 4; nt++) {
            float p0 = expf_fast(sacc[nt][0] - nm0);
            float p1 = expf_fast(sacc[nt][1] - nm0);
            float p2 = expf_fast(sacc[nt][2] - nm1);
            float p3 = expf_fast(sacc[nt][3] - nm1);
            rs0 += p0 + p1; rs1 += p2 + p3;
            pt[nt][0] = f2tf(p0); pt[nt][1] = f2tf(p1);
            pt[nt][2] = f2tf(p2); pt[nt][3] = f2tf(p3);
        }
        rs0 += __shfl_xor_sync(0xffffffffu, rs0, 1);
        rs0 += __shfl_xor_sync(0xffffffffu, rs0, 2);
        rs1 += __shfl_xor_sync(0xffffffffu, rs1, 1);
        rs1 += __shfl_xor_sync(0xffffffffu, rs1, 2);
        l0 = l0 * cf0 + rs0;
        l1 = l1 * cf1 + rs1;

        #pragma unroll
        for (int nt2 = 0; nt2 < 16; nt2++) {
            oacc[nt2][0] *= cf0; oacc[nt2][1] *= cf0;
            oacc[nt2][2] *= cf1; oacc[nt2][3] *= cf1;
        }

        // ---- P acc-frag -> A-frag permutation via shfl, then O += P*V
        const int src  = (lane & 0x1C) | (c >> 1);
        const int src2 = src + 2;
        #pragma unroll
        for (int ks2 = 0; ks2 < 4; ks2++) {
            uint32_t e0 = __shfl_sync(0xffffffffu, pt[ks2][0], src);
            uint32_t e1 = __shfl_sync(0xffffffffu, pt[ks2][1], src);
            uint32_t e2 = __shfl_sync(0xffffffffu, pt[ks2][2], src);
            uint32_t e3 = __shfl_sync(0xffffffffu, pt[ks2][3], src);
            uint32_t f0 = __shfl_sync(0xffffffffu, pt[ks2][0], src2);
            uint32_t f1 = __shfl_sync(0xffffffffu, pt[ks2][1], src2);
            uint32_t f2x = __shfl_sync(0xffffffffu, pt[ks2][2], src2);
            uint32_t f3 = __shfl_sync(0xffffffffu, pt[ks2][3], src2);
            uint32_t af[4];
            af[0] = (c & 1) ? e1 : e0;
            af[1] = (c & 1) ? e3 : e2;
            af[2] = (c & 1) ? f1 : f0;
            af[3] = (c & 1) ? f3 : f2x;
            #pragma unroll
            for (int nt2 = 0; nt2 < 16; nt2++) {
                const float* vp = Vs + (ks2 * 8 + c) * 132 + nt2 * 8 + g;
                uint32_t bf[2] = { __float_as_uint(vp[0]),
                                   __float_as_uint(vp[4 * 132]) };
                mma_tf32(oacc[nt2], af, bf);
            }
        }

        if (kt + 2 < nkt) kvissue(kt + 2);
        cp_commit();
    }

    // ---- epilogue: normalize, tf32-round (feeds proj GEMM), store
    float inv0 = 1.f / l0, inv1 = 1.f / l1;
    float* Yb = Y + ((size_t)b * T_ + (size_t)qt * 128) * C_ + h * HD_;
    const int lr0 = w * 16 + g;
    #pragma unroll
    for (int nt2 = 0; nt2 < 16; nt2++) {
        *(float2*)(Yb + (size_t)lr0 * C_ + nt2 * 8 + 2 * c) =
            make_float2(f2tf_f(oacc[nt2][0] * inv0), f2tf_f(oacc[nt2][1] * inv0));
        *(float2*)(Yb + (size_t)(lr0 + 8) * C_ + nt2 * 8 + 2 * c) =
            make_float2(f2tf_f(oacc[nt2][2] * inv1), f2tf_f(oacc[nt2][3] * inv1));
    }
}

// ---------------- launch --------------------------------------------------------
extern "C" void kernel_launch(void* const* d_in, const int* in_sizes, int n_in,
                              void* d_out, int out_size)
{
    const float* x     = (const float*)d_in[0];
    const float* rope  = (const float*)d_in[1];
    const float* Wqkv  = (const float*)d_in[2];
    const float* Wproj = (const float*)d_in[3];
    float* out = (float*)d_out;

    float *qkv, *q, *khi, *klo, *v, *y, *xtf, *wqkvT, *wprojT;
    cudaGetSymbolAddress((void**)&qkv,    g_qkv);
    cudaGetSymbolAddress((void**)&q,      g_q);
    cudaGetSymbolAddress((void**)&khi,    g_khi);
    cudaGetSymbolAddress((void**)&klo,    g_klo);
    cudaGetSymbolAddress((void**)&v,      g_v);
    cudaGetSymbolAddress((void**)&y,      g_y);
    cudaGetSymbolAddress((void**)&xtf,    g_xtf);
    cudaGetSymbolAddress((void**)&wqkvT,  g_wqkvT);
    cudaGetSymbolAddress((void**)&wprojT, g_wprojT);

    cudaFuncSetAttribute(gemm_tf32, cudaFuncAttributeMaxDynamicSharedMemorySize,
                         GSM_BYTES);
    cudaFuncSetAttribute(attn_tc, cudaFuncAttributeMaxDynamicSharedMemorySize,
                         ASM_BYTES);

    // 0) operand prep
    tf32_round_kernel<<<(B_ * T_ * C_ / 4) / 256, 256>>>(x, xtf);
    transpose_kernel<<<dim3((3 * C_) / 32, C_ / 32), 256>>>(Wqkv, wqkvT, C_, 3 * C_);
    transpose_kernel<<<dim3(C_ / 32, C_ / 32), 256>>>(Wproj, wprojT, C_, C_);

    // 1) qkv = x @ Wqkv
    gemm_tf32<<<dim3((B_ * T_) / 128, (3 * C_) / 256), 256, GSM_BYTES>>>(
        xtf, wqkvT, qkv, B_ * T_, 3 * C_, C_);

    // 2) RoPE + split-K + tf32 rounding
    rope_kernel<<<(B_ * T_ * H_ * (HD_ / 2)) / 256, 256>>>(qkv, rope, q, khi, klo, v);

    // 3) tensor-core causal flash attention -> y
    attn_tc<<<dim3(T_ / 128, B_ * H_), 256, ASM_BYTES>>>(q, khi, klo, v, y);

    // 4) out = y @ Wproj
    gemm_tf32<<<dim3((B_ * T_) / 128, C_ / 256), 256, GSM_BYTES>>>(
        y, wprojT, out, B_ * T_, C_, C_);
}

// round 10
// speedup vs baseline: 3.1074x; 1.0991x over previous
#include <cuda_runtime.h>
#include <cstdint>
#include <cstddef>

#define B_  4
#define T_  2048
#define C_  2048
#define H_  16
#define HD_ 128

// ---------------- scratch (static __device__ — no allocations allowed) ----------
__device__ float g_qkv[(size_t)B_ * T_ * 3 * C_];          // [B*T, 3C]
__device__ float g_q  [(size_t)B_ * H_ * T_ * HD_];        // [B,H,T,HD] tf32, pre-scaled
__device__ float g_khi[(size_t)B_ * H_ * T_ * HD_];        // K hi (tf32)
__device__ float g_klo[(size_t)B_ * H_ * T_ * HD_];        // K lo (tf32 of residual)
__device__ float g_v  [(size_t)B_ * H_ * T_ * HD_];        // V (tf32-rounded)
__device__ float g_y[(size_t)B_ * T_ * C_];                // attention out (tf32-rounded)
__device__ float g_xtf[(size_t)B_ * T_ * C_];              // x rounded to tf32
__device__ float g_wqkvT[(size_t)3 * C_ * C_];             // Wqkv^T  [3C, C] (tf32)
__device__ float g_wprojT[(size_t)C_ * C_];                // Wproj^T [C, C] (tf32)

// ---------------- small helpers -------------------------------------------------
__device__ __forceinline__ uint32_t f2tf(float x) {
    uint32_t u;
    asm("cvt.rna.tf32.f32 %0, %1;" : "=r"(u) : "f"(x));
    return u;
}
__device__ __forceinline__ float f2tf_f(float x) { return __uint_as_float(f2tf(x)); }

__device__ __forceinline__ void mma_tf32(float* d, const uint32_t* a,
                                         const uint32_t* b) {
    asm volatile(
        "mma.sync.aligned.m16n8k8.row.col.f32.tf32.tf32.f32 "
        "{%0,%1,%2,%3}, {%4,%5,%6,%7}, {%8,%9}, {%0,%1,%2,%3};"
        : "+f"(d[0]), "+f"(d[1]), "+f"(d[2]), "+f"(d[3])
        : "r"(a[0]), "r"(a[1]), "r"(a[2]), "r"(a[3]), "r"(b[0]), "r"(b[1]));
}
__device__ __forceinline__ uint32_t smem_u32(const void* p) {
    uint32_t a;
    asm("{ .reg .u64 t; cvta.to.shared.u64 t, %1; cvt.u32.u64 %0, t; }"
        : "=r"(a) : "l"(p));
    return a;
}
// ldmatrix x4: loads four 8x4-f32 blocks; per-lane addr = row of matrix (lane/8)
__device__ __forceinline__ void ldsm4(uint32_t* r, uint32_t addr) {
    asm volatile("ldmatrix.sync.aligned.m8n8.x4.shared.b16 {%0,%1,%2,%3}, [%4];"
                 : "=r"(r[0]), "=r"(r[1]), "=r"(r[2]), "=r"(r[3]) : "r"(addr));
}
__device__ __forceinline__ void cp16(uint32_t dst, const void* src) {
    asm volatile("cp.async.cg.shared.global [%0], [%1], 16;"
                 :: "r"(dst), "l"(src) : "memory");
}
__device__ __forceinline__ void cp_commit() {
    asm volatile("cp.async.commit_group;" ::: "memory");
}
template <int N>
__device__ __forceinline__ void cp_wait() {
    asm volatile("cp.async.wait_group %0;" :: "n"(N) : "memory");
}
// FFMA-pipe exp (keeps MUFU free; poly rel err ~2e-6)
__device__ __forceinline__ float expf_fast(float x) {
    float y = fmaxf(x, -60.f) * 1.4426950408889634f;
    float nf;
    asm("cvt.rni.f32.f32 %0, %1;" : "=f"(nf) : "f"(y));
    float f = y - nf;
    float p =              1.3333558e-3f;
    p = fmaf(p, f, 9.6181291e-3f);
    p = fmaf(p, f, 5.5504109e-2f);
    p = fmaf(p, f, 2.4022651e-1f);
    p = fmaf(p, f, 6.9314718e-1f);
    p = fmaf(p, f, 1.0f);
    return __int_as_float(__float_as_int(p) + (((int)nf) << 23));
}

// ===================== TF32 mma.sync GEMM (cp.async 4-stage + ldmatrix) =========
#define APITCH 20
#define ABUF_FLOATS (128 * APITCH)
#define BBUF_FLOATS (256 * APITCH)
#define BUF_FLOATS  (ABUF_FLOATS + BBUF_FLOATS)
#define STAGES 4
#define GSM_BYTES (STAGES * BUF_FLOATS * 4)

__global__ __launch_bounds__(256, 1) void gemm_tf32(
    const float* __restrict__ A, const float* __restrict__ Bt,
    float* __restrict__ Cm, int M, int N, int K)
{
    extern __shared__ float sm[];
    const uint32_t sbase = smem_u32(sm);
    const int tid  = threadIdx.x;
    const int wid  = tid >> 5;
    const int lane = tid & 31;
    const int g    = lane >> 2;
    const int c    = lane & 3;
    const int warp_m = wid & 1;
    const int warp_n = wid >> 1;

    const size_t m0 = (size_t)blockIdx.x * 128;
    const size_t n0 = (size_t)blockIdx.y * 256;

    // ldmatrix per-lane offsets (floats):
    // A frags: mat bit0 (lane>>3) -> +8 rows, bit1 (lane>>4) -> +4 cols
    const int aoff = (warp_m * 64 + (lane & 7) + ((lane >> 3) & 1) * 8) * APITCH
                   + ((lane >> 4) & 1) * 4;
    // B frags (nt pair): mat bit0 -> +4 cols (b0/b1), bit1 -> +8 rows (nt+1)
    const int boff = (warp_n * 64 + (lane & 7) + ((lane >> 4) & 1) * 8) * APITCH
                   + ((lane >> 3) & 1) * 4;

    const int ar[2]  = { (tid + 0)   >> 2, (tid + 256) >> 2 };
    const int akk[2] = { ((tid + 0)   & 3) << 2, ((tid + 256) & 3) << 2 };
    int br[4], bkk[4];
    #pragma unroll
    for (int j = 0; j < 4; j++) {
        br[j]  = (tid + j * 256) >> 2;
        bkk[j] = ((tid + j * 256) & 3) << 2;
    }

    float acc[4][8][4];
    #pragma unroll
    for (int mi = 0; mi < 4; mi++)
        #pragma unroll
        for (int ni = 0; ni < 8; ni++)
            #pragma unroll
            for (int q = 0; q < 4; q++) acc[mi][ni][q] = 0.f;

    const int niter = K >> 4;

    auto issue = [&](int it) {
        const int k0 = it << 4;
        const uint32_t As = sbase + (uint32_t)(it & (STAGES - 1)) * (BUF_FLOATS * 4);
        const uint32_t Bs = As + ABUF_FLOATS * 4;
        #pragma unroll
        for (int j = 0; j < 2; j++)
            cp16(As + (ar[j] * APITCH + akk[j]) * 4,
                 A + (m0 + ar[j]) * K + k0 + akk[j]);
        #pragma unroll
        for (int j = 0; j < 4; j++)
            cp16(Bs + (br[j] * APITCH + bkk[j]) * 4,
                 Bt + (n0 + br[j]) * K + k0 + bkk[j]);
    };

    #pragma unroll
    for (int s = 0; s < STAGES - 1; s++) {
        if (s < niter) issue(s);
        cp_commit();
    }

    for (int it = 0; it < niter; ++it) {
        cp_wait<STAGES - 2>();
        __syncthreads();

        const uint32_t As_u = sbase + (uint32_t)(it & (STAGES - 1)) * (BUF_FLOATS * 4);
        const uint32_t Bs_u = As_u + ABUF_FLOATS * 4;
        #pragma unroll
        for (int ks = 0; ks < 2; ks++) {
            uint32_t af[4][4], bf[4][4];
            #pragma unroll
            for (int mi = 0; mi < 4; mi++)
                ldsm4(af[mi], As_u + (aoff + mi * 16 * APITCH + ks * 8) * 4);
            #pragma unroll
            for (int np = 0; np < 4; np++)
                ldsm4(bf[np], Bs_u + (boff + np * 16 * APITCH + ks * 8) * 4);
            #pragma unroll
            for (int mi = 0; mi < 4; mi++)
                #pragma unroll
                for (int ni = 0; ni < 8; ni++)
                    mma_tf32(acc[mi][ni], af[mi], &bf[ni >> 1][(ni & 1) * 2]);
        }

        if (it + STAGES - 1 < niter) issue(it + STAGES - 1);
        cp_commit();
    }

    #pragma unroll
    for (int mi = 0; mi < 4; mi++) {
        const size_t row0 = m0 + warp_m * 64 + mi * 16 + g;
        #pragma unroll
        for (int ni = 0; ni < 8; ni++) {
            const size_t col = n0 + warp_n * 64 + ni * 8 + 2 * c;
            *(float2*)(Cm + row0 * N + col) =
                make_float2(acc[mi][ni][0], acc[mi][ni][1]);
            *(float2*)(Cm + (row0 + 8) * N + col) =
                make_float2(acc[mi][ni][2], acc[mi][ni][3]);
        }
    }
}

// ---------------- tf32 pre-round ------------------------------------------------
__global__ __launch_bounds__(256) void tf32_round_kernel(
    const float* __restrict__ in, float* __restrict__ out)
{
    int i = blockIdx.x * 256 + threadIdx.x;
    float4 v = ((const float4*)in)[i];
    v.x = f2tf_f(v.x); v.y = f2tf_f(v.y);
    v.z = f2tf_f(v.z); v.w = f2tf_f(v.w);
    ((float4*)out)[i] = v;
}

// ---------------- transpose + tf32 round ---------------------------------------
__global__ __launch_bounds__(256) void transpose_kernel(
    const float* __restrict__ in, float* __restrict__ out, int R, int Cc)
{
    __shared__ float tile[32][33];
    int c0 = blockIdx.x * 32, r0 = blockIdx.y * 32;
    int tx = threadIdx.x & 31, ty = threadIdx.x >> 5;
    #pragma unroll
    for (int j = 0; j < 4; j++)
        tile[ty + j * 8][tx] = in[(size_t)(r0 + ty + j * 8) * Cc + c0 + tx];
    __syncthreads();
    #pragma unroll
    for (int j = 0; j < 4; j++)
        out[(size_t)(c0 + ty + j * 8) * R + r0 + tx] = f2tf_f(tile[tx][ty + j * 8]);
}

// ---------------- RoPE: qkv -> q(scaled,tf32), khi, klo, v(tf32) ----------------
__global__ __launch_bounds__(256) void rope_kernel(
    const float* __restrict__ qkv, const float* __restrict__ rope,
    float* __restrict__ q, float* __restrict__ khi,
    float* __restrict__ klo, float* __restrict__ v)
{
    int idx = blockIdx.x * 256 + threadIdx.x;
    int p = idx & 63;
    int h = (idx >> 6) & 15;
    int t = (idx >> 10) & 2047;
    int b = idx >> 21;
    const float scale = 0.08838834764831845f;   // 1/sqrt(128)

    float2 cs = ((const float2*)rope)[t * 64 + p];
    size_t base_in = ((size_t)(b * T_ + t)) * (3 * C_) + h * HD_ + p * 2;
    float2 qv = *(const float2*)(qkv + base_in);
    float2 kv = *(const float2*)(qkv + base_in + C_);
    float2 vv = *(const float2*)(qkv + base_in + 2 * C_);

    float2 qo = make_float2((qv.x * cs.x - qv.y * cs.y) * scale,
                            (qv.y * cs.x + qv.x * cs.y) * scale);
    float2 ko = make_float2(kv.x * cs.x - kv.y * cs.y, kv.y * cs.x + kv.x * cs.y);

    float2 qr  = make_float2(f2tf_f(qo.x), f2tf_f(qo.y));
    float2 khv = make_float2(f2tf_f(ko.x), f2tf_f(ko.y));
    float2 klv = make_float2(f2tf_f(ko.x - khv.x), f2tf_f(ko.y - khv.y));
    float2 vr  = make_float2(f2tf_f(vv.x), f2tf_f(vv.y));

    size_t base_out = ((size_t)((b * H_ + h) * T_ + t)) * HD_ + p * 2;
    *(float2*)(q   + base_out) = qr;
    *(float2*)(khi + base_out) = khv;
    *(float2*)(klo + base_out) = klv;
    *(float2*)(v   + base_out) = vr;
}

// ================== Tensor-core flash attention (tf32, causal) ==================
// CTA: 128 q-rows, 8 warps x 16 rows, 256 threads. kt tiles of 32 keys.
// QK^T = Q*Khi + Q*Klo (split-K precision). PV single tf32 MMA.
// K frags via ldmatrix.x4 (pitch-132 rows -> conflict-free).
#define KV_TILE_F   (32 * 132)                  // 4224 floats
#define KV_STRIDE_F (3 * KV_TILE_F)             // 12672 floats per stage
#define ASM_BYTES   (3 * KV_STRIDE_F * 4)       // 152064 bytes

__global__ __launch_bounds__(256, 1) void attn_tc(
    const float* __restrict__ Qg, const float* __restrict__ Khig,
    const float* __restrict__ Klog, const float* __restrict__ Vg,
    float* __restrict__ Y)
{
    extern __shared__ float smn[];
    const uint32_t sbase = smem_u32(smn);
    const int qt = (int)gridDim.x - 1 - (int)blockIdx.x;   // heavy tiles first
    const int bh = blockIdx.y;
    const int b = bh >> 4, h = bh & 15;
    const int tid = threadIdx.x;
    const int w = tid >> 5, lane = tid & 31, g = lane >> 2, c = lane & 3;
    const size_t head = (size_t)bh * T_ * HD_;

    // K-frag ldmatrix lane offset: mat bit0 -> +4 cols (b0/b1), bit1 -> +8 rows
    const int koff = ((lane & 7) + ((lane >> 4) & 1) * 8) * 132
                   + ((lane >> 3) & 1) * 4;

    // ---- stage Q tile (already tf32+scaled) into smem pitch 132, extract frags
    {
        const float4* Qt = (const float4*)(Qg + head + (size_t)qt * 128 * HD_);
        for (int i = tid; i < 128 * 32; i += 256) {
            int r = i >> 5, d4 = (i & 31) << 2;
            float4 qv = Qt[i];
            float* dst = smn + r * 132 + d4;
            dst[0] = qv.x; dst[1] = qv.y; dst[2] = qv.z; dst[3] = qv.w;
        }
    }
    __syncthreads();
    uint32_t qf[16][4];
    {
        const float* q0 = smn + (w * 16 + g) * 132 + c;
        #pragma unroll
        for (int ks = 0; ks < 16; ks++) {
            qf[ks][0] = __float_as_uint(q0[ks * 8]);
            qf[ks][1] = __float_as_uint(q0[ks * 8 + 8 * 132]);
            qf[ks][2] = __float_as_uint(q0[ks * 8 + 4]);
            qf[ks][3] = __float_as_uint(q0[ks * 8 + 8 * 132 + 4]);
        }
    }
    __syncthreads();

    float oacc[16][4];
    #pragma unroll
    for (int i = 0; i < 16; i++) {
        oacc[i][0] = 0.f; oacc[i][1] = 0.f; oacc[i][2] = 0.f; oacc[i][3] = 0.f;
    }
    float m0v = -1e30f, m1v = -1e30f, l0 = 0.f, l1 = 0.f;

    const int nkt = qt * 4 + 4;
    const int cr = tid >> 3;              // copy row 0..31
    const int cc = (tid & 7) << 2;        // copy col base (floats)

    auto kvissue = [&](int kt) {
        uint32_t dstb = sbase + (uint32_t)(kt % 3) * (KV_STRIDE_F * 4)
                      + cr * (132 * 4);
        size_t srcb = head + ((size_t)kt * 32 + cr) * HD_;
        #pragma unroll
        for (int ch = 0; ch < 4; ch++) {
            uint32_t dst = dstb + (cc + ch * 32) * 4;
            size_t src = srcb + cc + ch * 32;
            cp16(dst,                     Khig + src);
            cp16(dst + KV_TILE_F * 4,     Klog + src);
            cp16(dst + 2 * KV_TILE_F * 4, Vg + src);
        }
    };
    kvissue(0); cp_commit();
    if (nkt > 1) kvissue(1);
    cp_commit();

    const int rg0 = qt * 128 + w * 16 + g;
    const int rg8 = rg0 + 8;

    for (int kt = 0; kt < nkt; kt++) {
        cp_wait<1>();
        __syncthreads();
        const uint32_t Khs_u = sbase + (uint32_t)(kt % 3) * (KV_STRIDE_F * 4);
        const uint32_t Kls_u = Khs_u + KV_TILE_F * 4;
        const float* Vs = smn + (kt % 3) * KV_STRIDE_F + 2 * KV_TILE_F;

        // ---- S = Q*Khi + Q*Klo  (16x32 per warp), K frags via ldmatrix
        float sacc[4][4];
        #pragma unroll
        for (int nt = 0; nt < 4; nt++) {
            sacc[nt][0] = 0.f; sacc[nt][1] = 0.f;
            sacc[nt][2] = 0.f; sacc[nt][3] = 0.f;
        }
        #pragma unroll
        for (int ks = 0; ks < 16; ks++) {
            uint32_t bh4[2][4], bl4[2][4];
            ldsm4(bh4[0], Khs_u + (koff + ks * 8) * 4);
            ldsm4(bh4[1], Khs_u + (koff + 16 * 132 + ks * 8) * 4);
            ldsm4(bl4[0], Kls_u + (koff + ks * 8) * 4);
            ldsm4(bl4[1], Kls_u + (koff + 16 * 132 + ks * 8) * 4);
            #pragma unroll
            for (int nt = 0; nt < 4; nt++) {
                mma_tf32(sacc[nt], qf[ks], &bh4[nt >> 1][(nt & 1) * 2]);
                mma_tf32(sacc[nt], qf[ks], &bl4[nt >> 1][(nt & 1) * 2]);
            }
        }

        // ---- causal mask (only when tile can cross the diagonal for this warp)
        if (kt * 32 + 31 > qt * 128 + w * 16) {
            #pragma unroll
            for (int nt = 0; nt < 4; nt++) {
                int col = kt * 32 + nt * 8 + 2 * c;
                if (col     > rg0) sacc[nt][0] = -1e30f;
                if (col + 1 > rg0) sacc[nt][1] = -1e30f;
                if (col     > rg8) sacc[nt][2] = -1e30f;
                if (col + 1 > rg8) sacc[nt][3] = -1e30f;
            }
        }

        // ---- online softmax (rows g, g+8; reduce over quad lanes)
        float mx0 = -1e30f, mx1 = -1e30f;
        #pragma unroll
        for (int nt = 0; nt < 4; nt++) {
            mx0 = fmaxf(mx0, fmaxf(sacc[nt][0], sacc[nt][1]));
            mx1 = fmaxf(mx1, fmaxf(sacc[nt][2], sacc[nt][3]));
        }
        mx0 = fmaxf(mx0, __shfl_xor_sync(0xffffffffu, mx0, 1));
        mx0 = fmaxf(mx0, __shfl_xor_sync(0xffffffffu, mx0, 2));
        mx1 = fmaxf(mx1, __shfl_xor_sync(0xffffffffu, mx1, 1));
        mx1 = fmaxf(mx1, __shfl_xor_sync(0xffffffffu, mx1, 2));
        float nm0 = fmaxf(m0v, mx0), nm1 = fmaxf(m1v, mx1);
        float cf0 = expf_fast(m0v - nm0), cf1 = expf_fast(m1v - nm1);
        m0v = nm0; m1v = nm1;

        uint32_t pt[4][4];
        float rs0 = 0.f, rs1 = 0.f;
        #pragma unroll
        for (int nt = 0; nt < 4; nt++) {
            float p0 = expf_fast(sacc[nt][0] - nm0);
            float p1 = expf_fast(sacc[nt][1] - nm0);
            float p2 = expf_fast(sacc[nt][2] - nm1);
            float p3 = expf_fast(sacc[nt][3] - nm1);
            rs0 += p0 + p1; rs1 += p2 + p3;
            pt[nt][0] = f2tf(p0); pt[nt][1] = f2tf(p1);
            pt[nt][2] = f2tf(p2); pt[nt][3] = f2tf(p3);
        }
        rs0 += __shfl_xor_sync(0xffffffffu, rs0, 1);
        rs0 += __shfl_xor_sync(0xffffffffu, rs0, 2);
        rs1 += __shfl_xor_sync(0xffffffffu, rs1, 1);
        rs1 += __shfl_xor_sync(0xffffffffu, rs1, 2);
        l0 = l0 * cf0 + rs0;
        l1 = l1 * cf1 + rs1;

        #pragma unroll
        for (int nt2 = 0; nt2 < 16; nt2++) {
            oacc[nt2][0] *= cf0; oacc[nt2][1] *= cf0;
            oacc[nt2][2] *= cf1; oacc[nt2][3] *= cf1;
        }

        // ---- P acc-frag -> A-frag permutation via shfl, then O += P*V
        const int src  = (lane & 0x1C) | (c >> 1);
        const int src2 = src + 2;
        #pragma unroll
        for (int ks2 = 0; ks2 < 4; ks2++) {
            uint32_t e0 = __shfl_sync(0xffffffffu, pt[ks2][0], src);
            uint32_t e1 = __shfl_sync(0xffffffffu, pt[ks2][1], src);
            uint32_t e2 = __shfl_sync(0xffffffffu, pt[ks2][2], src);
            uint32_t e3 = __shfl_sync(0xffffffffu, pt[ks2][3], src);
            uint32_t f0 = __shfl_sync(0xffffffffu, pt[ks2][0], src2);
            uint32_t f1 = __shfl_sync(0xffffffffu, pt[ks2][1], src2);
            uint32_t f2x = __shfl_sync(0xffffffffu, pt[ks2][2], src2);
            uint32_t f3 = __shfl_sync(0xffffffffu, pt[ks2][3], src2);
            uint32_t af[4];
            af[0] = (c & 1) ? e1 : e0;
            af[1] = (c & 1) ? e3 : e2;
            af[2] = (c & 1) ? f1 : f0;
            af[3] = (c & 1) ? f3 : f2x;
            #pragma unroll
            for (int nt2 = 0; nt2 < 16; nt2++) {
                const float* vp = Vs + (ks2 * 8 + c) * 132 + nt2 * 8 + g;
                uint32_t bf[2] = { __float_as_uint(vp[0]),
                                   __float_as_uint(vp[4 * 132]) };
                mma_tf32(oacc[nt2], af, bf);
            }
        }

        if (kt + 2 < nkt) kvissue(kt + 2);
        cp_commit();
    }

    // ---- epilogue: normalize, tf32-round (feeds proj GEMM), store
    float inv0 = 1.f / l0, inv1 = 1.f / l1;
    float* Yb = Y + ((size_t)b * T_ + (size_t)qt * 128) * C_ + h * HD_;
    const int lr0 = w * 16 + g;
    #pragma unroll
    for (int nt2 = 0; nt2 < 16; nt2++) {
        *(float2*)(Yb + (size_t)lr0 * C_ + nt2 * 8 + 2 * c) =
            make_float2(f2tf_f(oacc[nt2][0] * inv0), f2tf_f(oacc[nt2][1] * inv0));
        *(float2*)(Yb + (size_t)(lr0 + 8) * C_ + nt2 * 8 + 2 * c) =
            make_float2(f2tf_f(oacc[nt2][2] * inv1), f2tf_f(oacc[nt2][3] * inv1));
    }
}

// ---------------- launch --------------------------------------------------------
extern "C" void kernel_launch(void* const* d_in, const int* in_sizes, int n_in,
                              void* d_out, int out_size)
{
    const float* x     = (const float*)d_in[0];
    const float* rope  = (const float*)d_in[1];
    const float* Wqkv  = (const float*)d_in[2];
    const float* Wproj = (const float*)d_in[3];
    float* out = (float*)d_out;

    float *qkv, *q, *khi, *klo, *v, *y, *xtf, *wqkvT, *wprojT;
    cudaGetSymbolAddress((void**)&qkv,    g_qkv);
    cudaGetSymbolAddress((void**)&q,      g_q);
    cudaGetSymbolAddress((void**)&khi,    g_khi);
    cudaGetSymbolAddress((void**)&klo,    g_klo);
    cudaGetSymbolAddress((void**)&v,      g_v);
    cudaGetSymbolAddress((void**)&y,      g_y);
    cudaGetSymbolAddress((void**)&xtf,    g_xtf);
    cudaGetSymbolAddress((void**)&wqkvT,  g_wqkvT);
    cudaGetSymbolAddress((void**)&wprojT, g_wprojT);

    cudaFuncSetAttribute(gemm_tf32, cudaFuncAttributeMaxDynamicSharedMemorySize,
                         GSM_BYTES);
    cudaFuncSetAttribute(attn_tc, cudaFuncAttributeMaxDynamicSharedMemorySize,
                         ASM_BYTES);

    // 0) operand prep
    tf32_round_kernel<<<(B_ * T_ * C_ / 4) / 256, 256>>>(x, xtf);
    transpose_kernel<<<dim3((3 * C_) / 32, C_ / 32), 256>>>(Wqkv, wqkvT, C_, 3 * C_);
    transpose_kernel<<<dim3(C_ / 32, C_ / 32), 256>>>(Wproj, wprojT, C_, C_);

    // 1) qkv = x @ Wqkv
    gemm_tf32<<<dim3((B_ * T_) / 128, (3 * C_) / 256), 256, GSM_BYTES>>>(
        xtf, wqkvT, qkv, B_ * T_, 3 * C_, C_);

    // 2) RoPE + split-K + tf32 rounding
    rope_kernel<<<(B_ * T_ * H_ * (HD_ / 2)) / 256, 256>>>(qkv, rope, q, khi, klo, v);

    // 3) tensor-core causal flash attention -> y
    attn_tc<<<dim3(T_ / 128, B_ * H_), 256, ASM_BYTES>>>(q, khi, klo, v, y);

    // 4) out = y @ Wproj
    gemm_tf32<<<dim3((B_ * T_) / 128, C_ / 256), 256, GSM_BYTES>>>(
        y, wprojT, out, B_ * T_, C_, C_);
}